// round 14
// baseline (speedup 1.0000x reference)
#include <cuda_runtime.h>
#include <cuda_fp16.h>
#include <math.h>

#define NSTEPS 50
#define HT 40
#define XT 136
typedef unsigned u32;

__device__ float g_loc[4096], g_scale[4096];
__device__ float g_cond[6 * NSTEPS * 32], g_coef[NSTEPS * 5];
__device__ uint4 g_wA[6 * 3 * 2 * 2 * 4 * 32];
__device__ uint4 g_wE[6 * 2 * 2 * 4 * 32];
__device__ uint4 g_wIn[8 * 2 * 2 * 32];
__device__ uint4 g_wF[2 * 2 * 2 * 32];
__device__ uint4 g_wG[2 * 2 * 8 * 32];

__device__ __forceinline__ float sigm_f(float x) { return 1.0f / (1.0f + __expf(-x)); }
__device__ __forceinline__ float tanh_f(float x) { return 1.0f - 2.0f / (__expf(2.0f * x) + 1.0f); }
__device__ __forceinline__ void cpasync16(unsigned dst, const void* src) {
    asm volatile("cp.async.ca.shared.global [%0], [%1], 16;" :: "r"(dst), "l"(src));
}
__device__ __forceinline__ void mma16816(float c[4], const uint4& a, u32 b0, u32 b1) {
    asm("mma.sync.aligned.m16n8k16.row.col.f32.f16.f16.f32 "
        "{%0,%1,%2,%3}, {%4,%5,%6,%7}, {%8,%9}, {%0,%1,%2,%3};"
        : "+f"(c[0]), "+f"(c[1]), "+f"(c[2]), "+f"(c[3])
        : "r"(a.x), "r"(a.y), "r"(a.z), "r"(a.w), "r"(b0), "r"(b1));
}
__device__ __forceinline__ void wsplit(__half* hb, __half* lb, int idx, float v) {
    __half h = __float2half_rn(v);
    hb[idx] = h;
    lb[idx] = __float2half_rn(v - __half2float(h));
}
__device__ __forceinline__ u32 encpair(float w0, float w1, int var) {
    __half h0 = __float2half_rn(w0), h1 = __float2half_rn(w1);
    if (var) {
        h0 = __float2half_rn(w0 - __half2float(h0));
        h1 = __float2half_rn(w1 - __half2float(h1));
    }
    return (u32)__half_as_ushort(h0) | ((u32)__half_as_ushort(h1) << 16);
}
// Dual-accumulator 3x3: P gets AhBh+AlBh (6-MMA dep distance), Q gets AhBl.
__device__ __forceinline__ void mma3x3d(float accP[3][4], float accQ[3][4],
                                        const uint4& Ah, const uint4& Al,
                                        const __half* bhi, const __half* blo,
                                        int r0, int rs, int coff) {
    u32 bh0[3], bh1[3], bl0[3], bl1[3];
#pragma unroll
    for (int n = 0; n < 3; n++) {
        int c = (r0 + n * rs) * HT + coff;
        bh0[n] = *(const u32*)&bhi[c]; bh1[n] = *(const u32*)&bhi[c + 8];
        bl0[n] = *(const u32*)&blo[c]; bl1[n] = *(const u32*)&blo[c + 8];
    }
#pragma unroll
    for (int n = 0; n < 3; n++) mma16816(accP[n], Ah, bh0[n], bh1[n]);
#pragma unroll
    for (int n = 0; n < 3; n++) mma16816(accQ[n], Ah, bl0[n], bl1[n]);
#pragma unroll
    for (int n = 0; n < 3; n++) mma16816(accP[n], Al, bh0[n], bh1[n]);
}
#define ACC_INIT(P, Q, v0, v8)                                          \
    _Pragma("unroll") for (int n = 0; n < 3; n++) {                     \
        P[n][0] = v0; P[n][1] = v0; P[n][2] = v8; P[n][3] = v8;         \
        Q[n][0] = 0.f; Q[n][1] = 0.f; Q[n][2] = 0.f; Q[n][3] = 0.f;     \
    }
#define ACC_MERGE(P, Q)                                                 \
    _Pragma("unroll") for (int n = 0; n < 3; n++)                       \
        _Pragma("unroll") for (int q = 0; q < 4; q++) P[n][q] += Q[n][q];

__global__ void k_prep(const float* __restrict__ w_in, const float* __restrict__ lwd,
                       const float* __restrict__ lwo, const float* __restrict__ w_o1,
                       const float* __restrict__ w_o2) {
    int i = blockIdx.x * blockDim.x + threadIdx.x;
    int nt = gridDim.x * blockDim.x;
    for (int idx = i; idx < 6 * 3 * 2 * 2 * 4 * 32; idx += nt) {
        int lane = idx & 31, r = idx >> 5;
        int mt = r & 3; r >>= 2;
        int var = r & 1; r >>= 1;
        int kt = r & 1; r >>= 1;
        int tp = r % 3, l = r / 3;
        int og = 8 * mt + (lane >> 2), of = 32 + 8 * mt + (lane >> 2);
        int cb = kt * 16 + 2 * (lane & 3);
        auto w = [&](int o, int c) { return lwd[((l * 64 + o) * 32 + c) * 3 + tp]; };
        uint4 v;
        v.x = encpair(w(og, cb), w(og, cb + 1), var);
        v.y = encpair(w(of, cb), w(of, cb + 1), var);
        v.z = encpair(w(og, cb + 8), w(og, cb + 9), var);
        v.w = encpair(w(of, cb + 8), w(of, cb + 9), var);
        g_wA[idx] = v;
    }
    for (int idx = i; idx < 6 * 2 * 2 * 4 * 32; idx += nt) {
        int lane = idx & 31, r = idx >> 5;
        int mt = r & 3; r >>= 2;
        int var = r & 1; r >>= 1;
        int kt = r & 1; r >>= 1;
        int l = r;
        int o = 16 * mt + (lane >> 2);
        int cb = kt * 16 + 2 * (lane & 3);
        auto w = [&](int oo, int c) { return lwo[(l * 64 + oo) * 32 + c]; };
        uint4 v;
        v.x = encpair(w(o, cb), w(o, cb + 1), var);
        v.y = encpair(w(o + 8, cb), w(o + 8, cb + 1), var);
        v.z = encpair(w(o, cb + 8), w(o, cb + 9), var);
        v.w = encpair(w(o + 8, cb + 8), w(o + 8, cb + 9), var);
        g_wE[idx] = v;
    }
    for (int idx = i; idx < 8 * 2 * 2 * 32; idx += nt) {
        int lane = idx & 31, r = idx >> 5;
        int mt = r & 1; r >>= 1;
        int var = r & 1; r >>= 1;
        int kc = r;
        int o = 16 * mt + (lane >> 2);
        int cb = kc * 16 + 2 * (lane & 3);
        auto w = [&](int oo, int d) { return w_in[oo * 128 + d]; };
        uint4 v;
        v.x = encpair(w(o, cb), w(o, cb + 1), var);
        v.y = encpair(w(o + 8, cb), w(o + 8, cb + 1), var);
        v.z = encpair(w(o, cb + 8), w(o, cb + 9), var);
        v.w = encpair(w(o + 8, cb + 8), w(o + 8, cb + 9), var);
        g_wIn[idx] = v;
    }
    for (int idx = i; idx < 2 * 2 * 2 * 32; idx += nt) {
        int lane = idx & 31, r = idx >> 5;
        int mt = r & 1; r >>= 1;
        int var = r & 1; r >>= 1;
        int kt = r;
        int o = 16 * mt + (lane >> 2);
        int cb = kt * 16 + 2 * (lane & 3);
        const float s = 0.40824829046386302f;
        auto w = [&](int oo, int c) { return w_o1[oo * 32 + c] * s; };
        uint4 v;
        v.x = encpair(w(o, cb), w(o, cb + 1), var);
        v.y = encpair(w(o + 8, cb), w(o + 8, cb + 1), var);
        v.z = encpair(w(o, cb + 8), w(o, cb + 9), var);
        v.w = encpair(w(o + 8, cb + 8), w(o + 8, cb + 9), var);
        g_wF[idx] = v;
    }
    for (int idx = i; idx < 2 * 2 * 8 * 32; idx += nt) {
        int lane = idx & 31, r = idx >> 5;
        int mt8 = r & 7; r >>= 3;
        int var = r & 1; r >>= 1;
        int kt = r;
        int o = 16 * mt8 + (lane >> 2);
        int cb = kt * 16 + 2 * (lane & 3);
        auto w = [&](int oo, int c) { return w_o2[oo * 32 + c]; };
        uint4 v;
        v.x = encpair(w(o, cb), w(o, cb + 1), var);
        v.y = encpair(w(o + 8, cb), w(o + 8, cb + 1), var);
        v.z = encpair(w(o, cb + 8), w(o, cb + 9), var);
        v.w = encpair(w(o + 8, cb + 8), w(o + 8, cb + 9), var);
        g_wG[idx] = v;
    }
    if (i == 0) {
        double abar = 1.0;
        for (int t = 0; t < NSTEPS; t++) {
            double beta = 1e-4 + (double)t * (0.1 - 1e-4) / 49.0;
            double alpha = 1.0 - beta, abp = abar;
            abar *= alpha;
            double om = 1.0 - abar;
            g_coef[t * 5 + 0] = (float)sqrt(om);
            g_coef[t * 5 + 1] = (float)(1.0 / sqrt(abar));
            g_coef[t * 5 + 2] = (float)(beta * sqrt(abp) / om);
            g_coef[t * 5 + 3] = (float)((1.0 - abp) * sqrt(alpha) / om);
            double pv = beta * (1.0 - abp) / om;
            g_coef[t * 5 + 4] = (t > 0) ? (float)sqrt(pv) : 0.0f;
        }
    }
}

__global__ void k_stats(const float* __restrict__ x_hist) {
    int b = blockIdx.x, d = threadIdx.x;
    const float* xb = x_hist + (size_t)b * 192 * 128 + d;
    double s = 0.0;
    for (int t = 0; t < 192; t++) s += (double)xb[t * 128];
    float mean = (float)(s / 192.0);
    float c = xb[0] - mean;
    float v = c * c;
    for (int t = 1; t < 192; t++) {
        float cc = xb[t * 128] - mean;
        v = 0.94f * v + 0.06f * (cc * cc);
    }
    g_loc[b * 128 + d] = mean;
    g_scale[b * 128 + d] = fmaxf(sqrtf(v * 0.5f), 1e-5f);
}

__global__ void k_temb(const float* __restrict__ w1, const float* __restrict__ b1,
                       const float* __restrict__ w2, const float* __restrict__ b2,
                       const float* __restrict__ wt, const float* __restrict__ bt) {
    __shared__ float pe[128], te1[512], te2[512];
    int t = blockIdx.x, tid = threadIdx.x;
    if (tid < 64) {
        float y = ((float)tid * 4.0f) / 63.0f;
        float p = (float)pow(10.0, (double)y);
        float e = (float)t * p;
        pe[tid] = (float)sin((double)e);
        pe[tid + 64] = (float)cos((double)e);
    }
    __syncthreads();
    {
        double a = (double)b1[tid];
        for (int j = 0; j < 128; j++) a += (double)pe[j] * (double)w1[j * 512 + tid];
        te1[tid] = (float)(a / (1.0 + exp(-a)));
    }
    __syncthreads();
    {
        double a = (double)b2[tid];
        for (int k = 0; k < 512; k++) a += (double)te1[k] * (double)w2[k * 512 + tid];
        te2[tid] = (float)(a / (1.0 + exp(-a)));
    }
    __syncthreads();
    if (tid < 192) {
        int l = tid >> 5, c = tid & 31;
        double a = (double)bt[l * 32 + c];
        for (int k = 0; k < 512; k++) a += (double)te2[k] * (double)wt[(l * 512 + k) * 32 + c];
        g_cond[(l * NSTEPS + t) * 32 + c] = (float)a;
    }
}

template <int DIL>
__device__ __forceinline__ void conv_mma(const __half* hT_hi, const __half* hT_lo,
                                         __half* aT_hi, __half* aT_lo,
                                         const float* __restrict__ bdil,
                                         int l, int w, int lane) {
    const int frow = lane >> 2, fcol = 2 * (lane & 3);
    float bg = bdil[l * 64 + 8 * w + frow], bf = bdil[l * 64 + 32 + 8 * w + frow];
    float accP[3][4], accQ[3][4];
    ACC_INIT(accP, accQ, bg, bf)
#pragma unroll
    for (int tp = 0; tp < 3; tp++)
#pragma unroll
        for (int kt = 0; kt < 2; kt++) {
            int base = ((((l * 3 + tp) * 2 + kt) * 2) * 4 + w) * 32 + lane;
            uint4 Ah = g_wA[base], Al = g_wA[base + 128];
            mma3x3d(accP, accQ, Ah, Al, hT_hi, hT_lo,
                    32 + frow + (tp - 1) * DIL, 8, kt * 16 + fcol);
        }
    ACC_MERGE(accP, accQ)
    int o = 8 * w + frow;
#pragma unroll
    for (int n = 0; n < 3; n++) {
        int j = n * 8 + fcol;
        wsplit(aT_hi, aT_lo, j * HT + o, tanh_f(accP[n][2]) * sigm_f(accP[n][0]));
        wsplit(aT_hi, aT_lo, (j + 1) * HT + o, tanh_f(accP[n][3]) * sigm_f(accP[n][1]));
    }
}

__global__ __launch_bounds__(128, 4) void k_main(
    const float* __restrict__ z_init, const float* __restrict__ noise,
    const float* __restrict__ b_in, const float* __restrict__ bdil,
    const float* __restrict__ bout, const float* __restrict__ b_o1,
    const float* __restrict__ b_o2, float* __restrict__ out) {
    extern __shared__ __align__(16) char dyn[];
    __half* hT_hi = (__half*)dyn;
    __half* hT_lo = (__half*)(dyn + 7040);
    __half* aT_hi = (__half*)(dyn + 14080);
    __half* aT_lo = (__half*)(dyn + 16000);
    __half* skT_hi = (__half*)(dyn + 17920);
    __half* skT_lo = (__half*)(dyn + 19840);
    __half* xT_hi = (__half*)(dyn + 21760);
    __half* xT_lo = (__half*)(dyn + 28288);
    float* nzS = (float*)(dyn + 34816);   // 12288 -> 47104

    const int tid = threadIdx.x, chain = blockIdx.x;
    const int lane = tid & 31, warp = tid >> 5;
    const int frow = lane >> 2, fcol = 2 * (lane & 3);
    const unsigned nz_dst = (unsigned)__cvta_generic_to_shared(&nzS[tid * 24]);

    {
        const float4* zp = (const float4*)(z_init + (size_t)chain * 3072);
#pragma unroll
        for (int q = 0; q < 6; q++) {
            float4 v = zp[tid * 6 + q];
            int j = 4 * q;
            wsplit(xT_hi, xT_lo, j * XT + tid, v.x);
            wsplit(xT_hi, xT_lo, (j + 1) * XT + tid, v.y);
            wsplit(xT_hi, xT_lo, (j + 2) * XT + tid, v.z);
            wsplit(xT_hi, xT_lo, (j + 3) * XT + tid, v.w);
        }
    }
    for (int i = tid; i < 88 * HT / 2; i += 128) { ((u32*)hT_hi)[i] = 0u; ((u32*)hT_lo)[i] = 0u; }
    __syncthreads();

    float fR[3][4];

    for (int t = NSTEPS - 1; t >= 0; t--) {
        const float s1m = g_coef[t * 5], isab = g_coef[t * 5 + 1];
        const float c0 = g_coef[t * 5 + 2], cxt = g_coef[t * 5 + 3], sg = g_coef[t * 5 + 4];
        {
            const float* nsrc = noise + ((size_t)(NSTEPS - 1 - t) * 512 + chain) * 3072 + (size_t)tid * 24;
#pragma unroll
            for (int q = 0; q < 6; q++) cpasync16(nz_dst + 16 * q, nsrc + 4 * q);
            asm volatile("cp.async.commit_group;");
        }
        // A: h = relu(W_in @ x + b), warps 0-1 (fragments = res-warp h state)
        if (warp < 2) {
            int c = 16 * warp + frow;
            float b0 = b_in[c], b8 = b_in[c + 8];
            float cn0 = g_cond[t * 32 + c], cn8 = g_cond[t * 32 + c + 8];
            float accP[3][4], accQ[3][4];
            ACC_INIT(accP, accQ, b0, b8)
#pragma unroll
            for (int kc = 0; kc < 8; kc++) {
                int base = ((kc * 2) * 2 + warp) * 32 + lane;
                uint4 Ah = g_wIn[base], Al = g_wIn[base + 64];
                u32 bh0[3], bh1[3], bl0[3], bl1[3];
#pragma unroll
                for (int n = 0; n < 3; n++) {
                    int coff = (n * 8 + frow) * XT + kc * 16 + fcol;
                    bh0[n] = *(const u32*)&xT_hi[coff]; bh1[n] = *(const u32*)&xT_hi[coff + 8];
                    bl0[n] = *(const u32*)&xT_lo[coff]; bl1[n] = *(const u32*)&xT_lo[coff + 8];
                }
#pragma unroll
                for (int n = 0; n < 3; n++) mma16816(accP[n], Ah, bh0[n], bh1[n]);
#pragma unroll
                for (int n = 0; n < 3; n++) mma16816(accQ[n], Ah, bl0[n], bl1[n]);
#pragma unroll
                for (int n = 0; n < 3; n++) mma16816(accP[n], Al, bh0[n], bh1[n]);
            }
            ACC_MERGE(accP, accQ)
#pragma unroll
            for (int n = 0; n < 3; n++) {
                int j = n * 8 + fcol;
#pragma unroll
                for (int q = 0; q < 4; q++) fR[n][q] = fmaxf(accP[n][q], 0.f);
                wsplit(hT_hi, hT_lo, (32 + j) * HT + c, fR[n][0] + cn0);
                wsplit(hT_hi, hT_lo, (33 + j) * HT + c, fR[n][1] + cn0);
                wsplit(hT_hi, hT_lo, (32 + j) * HT + c + 8, fR[n][2] + cn8);
                wsplit(hT_hi, hT_lo, (33 + j) * HT + c + 8, fR[n][3] + cn8);
            }
        } else {
#pragma unroll
            for (int n = 0; n < 3; n++) { fR[n][0] = 0.f; fR[n][1] = 0.f; fR[n][2] = 0.f; fR[n][3] = 0.f; }
        }
        __syncthreads();

        for (int l = 0; l < 6; l++) {
            switch (l) {
                case 0: conv_mma<1>(hT_hi, hT_lo, aT_hi, aT_lo, bdil, l, warp, lane); break;
                case 1: conv_mma<2>(hT_hi, hT_lo, aT_hi, aT_lo, bdil, l, warp, lane); break;
                case 2: conv_mma<4>(hT_hi, hT_lo, aT_hi, aT_lo, bdil, l, warp, lane); break;
                case 3: conv_mma<8>(hT_hi, hT_lo, aT_hi, aT_lo, bdil, l, warp, lane); break;
                case 4: conv_mma<16>(hT_hi, hT_lo, aT_hi, aT_lo, bdil, l, warp, lane); break;
                default: conv_mma<32>(hT_hi, hT_lo, aT_hi, aT_lo, bdil, l, warp, lane); break;
            }
            __syncthreads();
            {
                bool resw = (warp < 2);
                if (resw ? (l < 5) : true) {
                    int c = resw ? 16 * warp + frow : 16 * (warp - 2) + frow;
                    int ob = resw ? c : 32 + c;
                    float b0 = bout[l * 64 + ob], b8 = bout[l * 64 + ob + 8];
                    float accP[3][4], accQ[3][4];
                    ACC_INIT(accP, accQ, b0, b8)
#pragma unroll
                    for (int kt = 0; kt < 2; kt++) {
                        int base = (((l * 2 + kt) * 2) * 4 + warp) * 32 + lane;
                        uint4 Ah = g_wE[base], Al = g_wE[base + 128];
                        mma3x3d(accP, accQ, Ah, Al, aT_hi, aT_lo, frow, 8, kt * 16 + fcol);
                    }
                    ACC_MERGE(accP, accQ)
                    if (resw) {
                        float cn0 = g_cond[((l + 1) * NSTEPS + t) * 32 + c];
                        float cn8 = g_cond[((l + 1) * NSTEPS + t) * 32 + c + 8];
#pragma unroll
                        for (int n = 0; n < 3; n++) {
                            int j = n * 8 + fcol;
#pragma unroll
                            for (int q = 0; q < 4; q++)
                                fR[n][q] = (fR[n][q] + accP[n][q]) * 0.70710678118654752f;
                            wsplit(hT_hi, hT_lo, (32 + j) * HT + c, fR[n][0] + cn0);
                            wsplit(hT_hi, hT_lo, (33 + j) * HT + c, fR[n][1] + cn0);
                            wsplit(hT_hi, hT_lo, (32 + j) * HT + c + 8, fR[n][2] + cn8);
                            wsplit(hT_hi, hT_lo, (33 + j) * HT + c + 8, fR[n][3] + cn8);
                        }
                    } else {
#pragma unroll
                        for (int n = 0; n < 3; n++) {
#pragma unroll
                            for (int q = 0; q < 4; q++) fR[n][q] += accP[n][q];
                        }
                        if (l == 5) {
#pragma unroll
                            for (int n = 0; n < 3; n++) {
                                int j = n * 8 + fcol;
                                wsplit(skT_hi, skT_lo, j * HT + c, fR[n][0]);
                                wsplit(skT_hi, skT_lo, (j + 1) * HT + c, fR[n][1]);
                                wsplit(skT_hi, skT_lo, j * HT + c + 8, fR[n][2]);
                                wsplit(skT_hi, skT_lo, (j + 1) * HT + c + 8, fR[n][3]);
                            }
                        }
                    }
                }
            }
            __syncthreads();
        }
        // F: s = relu(W_o1 @ skip/sqrt6 + b), warps 0-1 -> aT
        if (warp < 2) {
            int c = 16 * warp + frow;
            float b0 = b_o1[c], b8 = b_o1[c + 8];
            float accP[3][4], accQ[3][4];
            ACC_INIT(accP, accQ, b0, b8)
#pragma unroll
            for (int kt = 0; kt < 2; kt++) {
                int base = ((kt * 2) * 2 + warp) * 32 + lane;
                uint4 Ah = g_wF[base], Al = g_wF[base + 64];
                mma3x3d(accP, accQ, Ah, Al, skT_hi, skT_lo, frow, 8, kt * 16 + fcol);
            }
            ACC_MERGE(accP, accQ)
#pragma unroll
            for (int n = 0; n < 3; n++) {
                int j = n * 8 + fcol;
                wsplit(aT_hi, aT_lo, j * HT + c, fmaxf(accP[n][0], 0.f));
                wsplit(aT_hi, aT_lo, (j + 1) * HT + c, fmaxf(accP[n][1], 0.f));
                wsplit(aT_hi, aT_lo, j * HT + c + 8, fmaxf(accP[n][2], 0.f));
                wsplit(aT_hi, aT_lo, (j + 1) * HT + c + 8, fmaxf(accP[n][3], 0.f));
            }
        }
        __syncthreads();
        // G: eps = W_o2 @ s (all warps, 2 m-tiles); DDPM update of split-x
#pragma unroll
        for (int m = 0; m < 2; m++) {
            int mt8 = 2 * warp + m, dbase = 16 * mt8;
            float b0 = b_o2[dbase + frow], b8 = b_o2[dbase + frow + 8];
            float accP[3][4], accQ[3][4];
            ACC_INIT(accP, accQ, b0, b8)
#pragma unroll
            for (int kt = 0; kt < 2; kt++) {
                int base = ((kt * 2) * 8 + mt8) * 32 + lane;
                uint4 Ah = g_wG[base], Al = g_wG[base + 256];
                mma3x3d(accP, accQ, Ah, Al, aT_hi, aT_lo, frow, 8, kt * 16 + fcol);
            }
            ACC_MERGE(accP, accQ)
            if (m == 0) asm volatile("cp.async.wait_group 0;" ::: "memory");
#pragma unroll
            for (int n = 0; n < 3; n++)
#pragma unroll
                for (int r = 0; r < 2; r++)
#pragma unroll
                    for (int e = 0; e < 2; e++) {
                        int d = dbase + frow + 8 * r;
                        int j = n * 8 + fcol + e;
                        int xa = j * XT + d;
                        float x = __half2float(xT_hi[xa]) + __half2float(xT_lo[xa]);
                        float nz = nzS[d * 24 + j];
                        float eps = accP[n][2 * r + e];
                        float x0 = fminf(fmaxf((x - s1m * eps) * isab, -1.f), 1.f);
                        float xn = fmaf(c0, x0, fmaf(cxt, x, sg * nz));
                        wsplit(xT_hi, xT_lo, xa, xn);
                    }
        }
        __syncthreads();
    }
    {
        int b = chain & 31;
        float lc = g_loc[b * 128 + tid];
        float scl = g_scale[b * 128 + tid];
        for (int hh = 0; hh < 24; hh++) {
            int xa = hh * XT + tid;
            double z = (double)(__half2float(xT_hi[xa]) + __half2float(xT_lo[xa]));
            double u = 0.5 * erfc(-z * 0.70710678118654752440);
            u = fmin(fmax(u, 1e-6), 1.0 - 1e-6);
            double a = 4.0 * u * (1.0 - u);
            a = fmin(fmax(a, 1e-12), 1.0);
            double r = sqrt(a);
            double q = 2.0 * sqrt(fmax(cos(acos(r) / 3.0) / r - 1.0, 0.0));
            double sgn = (u >= 0.5) ? 1.0 : -1.0;
            out[((size_t)chain * 24 + hh) * 128 + tid] = (float)((double)lc + (double)scl * sgn * q);
        }
    }
}

extern "C" void kernel_launch(void* const* d_in, const int* in_sizes, int n_in,
                              void* d_out, int out_size) {
    const float* x_hist = (const float*)d_in[0];
    const float* z_init = (const float*)d_in[1];
    const float* noise = (const float*)d_in[2];
    const float* w_in = (const float*)d_in[3];
    const float* b_in = (const float*)d_in[4];
    const float* tw1 = (const float*)d_in[5];
    const float* tb1 = (const float*)d_in[6];
    const float* tw2 = (const float*)d_in[7];
    const float* tb2 = (const float*)d_in[8];
    const float* lwt = (const float*)d_in[9];
    const float* lbt = (const float*)d_in[10];
    const float* lwd = (const float*)d_in[11];
    const float* lbd = (const float*)d_in[12];
    const float* lwo = (const float*)d_in[13];
    const float* lbo = (const float*)d_in[14];
    const float* w_o1 = (const float*)d_in[15];
    const float* b_o1 = (const float*)d_in[16];
    const float* w_o2 = (const float*)d_in[17];
    const float* b_o2 = (const float*)d_in[18];
    float* out = (float*)d_out;

    const int SMEM = 47104;
    cudaFuncSetAttribute(k_main, cudaFuncAttributeMaxDynamicSharedMemorySize, SMEM);
    k_prep<<<64, 256>>>(w_in, lwd, lwo, w_o1, w_o2);
    k_stats<<<32, 128>>>(x_hist);
    k_temb<<<50, 512>>>(tw1, tb1, tw2, tb2, lwt, lbt);
    k_main<<<512, 128, SMEM>>>(z_init, noise, b_in, lbd, lbo, b_o1, b_o2, out);
}

// round 15
// speedup vs baseline: 1.1919x; 1.1919x over previous
#include <cuda_runtime.h>
#include <cuda_fp16.h>
#include <math.h>

#define NSTEPS 50
#define HT 40
#define XT 136
typedef unsigned u32;

__device__ float g_loc[4096], g_scale[4096];
__device__ float g_cond[6 * NSTEPS * 32], g_coef[NSTEPS * 5];
__device__ uint4 g_wA[6 * 3 * 2 * 2 * 4 * 32];
__device__ uint4 g_wE[6 * 2 * 2 * 4 * 32];
__device__ uint4 g_wIn[8 * 2 * 2 * 32];
__device__ uint4 g_wF[2 * 2 * 2 * 32];
__device__ uint4 g_wG[2 * 2 * 8 * 32];

__device__ __forceinline__ float tanh_hw(float x) {
    float y; asm("tanh.approx.f32 %0, %1;" : "=f"(y) : "f"(x)); return y;
}
__device__ __forceinline__ float sigm_hw(float x) {
    return fmaf(0.5f, tanh_hw(0.5f * x), 0.5f);
}
__device__ __forceinline__ void cpasync16(unsigned dst, const void* src) {
    asm volatile("cp.async.ca.shared.global [%0], [%1], 16;" :: "r"(dst), "l"(src));
}
__device__ __forceinline__ void mma16816(float c[4], const uint4& a, u32 b0, u32 b1) {
    asm("mma.sync.aligned.m16n8k16.row.col.f32.f16.f16.f32 "
        "{%0,%1,%2,%3}, {%4,%5,%6,%7}, {%8,%9}, {%0,%1,%2,%3};"
        : "+f"(c[0]), "+f"(c[1]), "+f"(c[2]), "+f"(c[3])
        : "r"(a.x), "r"(a.y), "r"(a.z), "r"(a.w), "r"(b0), "r"(b1));
}
__device__ __forceinline__ void wsplit(__half* hb, __half* lb, int idx, float v) {
    __half h = __float2half_rn(v);
    hb[idx] = h;
    lb[idx] = __float2half_rn(v - __half2float(h));
}
__device__ __forceinline__ u32 encpair(float w0, float w1, int var) {
    __half h0 = __float2half_rn(w0), h1 = __float2half_rn(w1);
    if (var) {
        h0 = __float2half_rn(w0 - __half2float(h0));
        h1 = __float2half_rn(w1 - __half2float(h1));
    }
    return (u32)__half_as_ushort(h0) | ((u32)__half_as_ushort(h1) << 16);
}
// 3 n-tiles, grouped by term (AhBh x3, AhBl x3, AlBh x3), single accumulator set.
__device__ __forceinline__ void mma3x3(float acc[3][4], const uint4& Ah, const uint4& Al,
                                       const __half* bhi, const __half* blo,
                                       int r0, int rs, int coff) {
    u32 bh0[3], bh1[3], bl0[3], bl1[3];
#pragma unroll
    for (int n = 0; n < 3; n++) {
        int c = (r0 + n * rs) * HT + coff;
        bh0[n] = *(const u32*)&bhi[c]; bh1[n] = *(const u32*)&bhi[c + 8];
        bl0[n] = *(const u32*)&blo[c]; bl1[n] = *(const u32*)&blo[c + 8];
    }
#pragma unroll
    for (int n = 0; n < 3; n++) mma16816(acc[n], Ah, bh0[n], bh1[n]);
#pragma unroll
    for (int n = 0; n < 3; n++) mma16816(acc[n], Ah, bl0[n], bl1[n]);
#pragma unroll
    for (int n = 0; n < 3; n++) mma16816(acc[n], Al, bh0[n], bh1[n]);
}

__global__ void k_prep(const float* __restrict__ w_in, const float* __restrict__ lwd,
                       const float* __restrict__ lwo, const float* __restrict__ w_o1,
                       const float* __restrict__ w_o2) {
    int i = blockIdx.x * blockDim.x + threadIdx.x;
    int nt = gridDim.x * blockDim.x;
    for (int idx = i; idx < 6 * 3 * 2 * 2 * 4 * 32; idx += nt) {
        int lane = idx & 31, r = idx >> 5;
        int mt = r & 3; r >>= 2;
        int var = r & 1; r >>= 1;
        int kt = r & 1; r >>= 1;
        int tp = r % 3, l = r / 3;
        int og = 8 * mt + (lane >> 2), of = 32 + 8 * mt + (lane >> 2);
        int cb = kt * 16 + 2 * (lane & 3);
        auto w = [&](int o, int c) { return lwd[((l * 64 + o) * 32 + c) * 3 + tp]; };
        uint4 v;
        v.x = encpair(w(og, cb), w(og, cb + 1), var);
        v.y = encpair(w(of, cb), w(of, cb + 1), var);
        v.z = encpair(w(og, cb + 8), w(og, cb + 9), var);
        v.w = encpair(w(of, cb + 8), w(of, cb + 9), var);
        g_wA[idx] = v;
    }
    for (int idx = i; idx < 6 * 2 * 2 * 4 * 32; idx += nt) {
        int lane = idx & 31, r = idx >> 5;
        int mt = r & 3; r >>= 2;
        int var = r & 1; r >>= 1;
        int kt = r & 1; r >>= 1;
        int l = r;
        int o = 16 * mt + (lane >> 2);
        int cb = kt * 16 + 2 * (lane & 3);
        auto w = [&](int oo, int c) { return lwo[(l * 64 + oo) * 32 + c]; };
        uint4 v;
        v.x = encpair(w(o, cb), w(o, cb + 1), var);
        v.y = encpair(w(o + 8, cb), w(o + 8, cb + 1), var);
        v.z = encpair(w(o, cb + 8), w(o, cb + 9), var);
        v.w = encpair(w(o + 8, cb + 8), w(o + 8, cb + 9), var);
        g_wE[idx] = v;
    }
    for (int idx = i; idx < 8 * 2 * 2 * 32; idx += nt) {
        int lane = idx & 31, r = idx >> 5;
        int mt = r & 1; r >>= 1;
        int var = r & 1; r >>= 1;
        int kc = r;
        int o = 16 * mt + (lane >> 2);
        int cb = kc * 16 + 2 * (lane & 3);
        auto w = [&](int oo, int d) { return w_in[oo * 128 + d]; };
        uint4 v;
        v.x = encpair(w(o, cb), w(o, cb + 1), var);
        v.y = encpair(w(o + 8, cb), w(o + 8, cb + 1), var);
        v.z = encpair(w(o, cb + 8), w(o, cb + 9), var);
        v.w = encpair(w(o + 8, cb + 8), w(o + 8, cb + 9), var);
        g_wIn[idx] = v;
    }
    for (int idx = i; idx < 2 * 2 * 2 * 32; idx += nt) {
        int lane = idx & 31, r = idx >> 5;
        int mt = r & 1; r >>= 1;
        int var = r & 1; r >>= 1;
        int kt = r;
        int o = 16 * mt + (lane >> 2);
        int cb = kt * 16 + 2 * (lane & 3);
        const float s = 0.40824829046386302f;
        auto w = [&](int oo, int c) { return w_o1[oo * 32 + c] * s; };
        uint4 v;
        v.x = encpair(w(o, cb), w(o, cb + 1), var);
        v.y = encpair(w(o + 8, cb), w(o + 8, cb + 1), var);
        v.z = encpair(w(o, cb + 8), w(o, cb + 9), var);
        v.w = encpair(w(o + 8, cb + 8), w(o + 8, cb + 9), var);
        g_wF[idx] = v;
    }
    for (int idx = i; idx < 2 * 2 * 8 * 32; idx += nt) {
        int lane = idx & 31, r = idx >> 5;
        int mt8 = r & 7; r >>= 3;
        int var = r & 1; r >>= 1;
        int kt = r;
        int o = 16 * mt8 + (lane >> 2);
        int cb = kt * 16 + 2 * (lane & 3);
        auto w = [&](int oo, int c) { return w_o2[oo * 32 + c]; };
        uint4 v;
        v.x = encpair(w(o, cb), w(o, cb + 1), var);
        v.y = encpair(w(o + 8, cb), w(o + 8, cb + 1), var);
        v.z = encpair(w(o, cb + 8), w(o, cb + 9), var);
        v.w = encpair(w(o + 8, cb + 8), w(o + 8, cb + 9), var);
        g_wG[idx] = v;
    }
    if (i == 0) {
        double abar = 1.0;
        for (int t = 0; t < NSTEPS; t++) {
            double beta = 1e-4 + (double)t * (0.1 - 1e-4) / 49.0;
            double alpha = 1.0 - beta, abp = abar;
            abar *= alpha;
            double om = 1.0 - abar;
            g_coef[t * 5 + 0] = (float)sqrt(om);
            g_coef[t * 5 + 1] = (float)(1.0 / sqrt(abar));
            g_coef[t * 5 + 2] = (float)(beta * sqrt(abp) / om);
            g_coef[t * 5 + 3] = (float)((1.0 - abp) * sqrt(alpha) / om);
            double pv = beta * (1.0 - abp) / om;
            g_coef[t * 5 + 4] = (t > 0) ? (float)sqrt(pv) : 0.0f;
        }
    }
}

__global__ void k_stats(const float* __restrict__ x_hist) {
    int b = blockIdx.x, d = threadIdx.x;
    const float* xb = x_hist + (size_t)b * 192 * 128 + d;
    double s = 0.0;
    for (int t = 0; t < 192; t++) s += (double)xb[t * 128];
    float mean = (float)(s / 192.0);
    float c = xb[0] - mean;
    float v = c * c;
    for (int t = 1; t < 192; t++) {
        float cc = xb[t * 128] - mean;
        v = 0.94f * v + 0.06f * (cc * cc);
    }
    g_loc[b * 128 + d] = mean;
    g_scale[b * 128 + d] = fmaxf(sqrtf(v * 0.5f), 1e-5f);
}

__global__ void k_temb(const float* __restrict__ w1, const float* __restrict__ b1,
                       const float* __restrict__ w2, const float* __restrict__ b2,
                       const float* __restrict__ wt, const float* __restrict__ bt) {
    __shared__ float pe[128], te1[512], te2[512];
    int t = blockIdx.x, tid = threadIdx.x;
    if (tid < 64) {
        float y = ((float)tid * 4.0f) / 63.0f;
        float p = (float)pow(10.0, (double)y);
        float e = (float)t * p;
        pe[tid] = (float)sin((double)e);
        pe[tid + 64] = (float)cos((double)e);
    }
    __syncthreads();
    {
        double a = (double)b1[tid];
        for (int j = 0; j < 128; j++) a += (double)pe[j] * (double)w1[j * 512 + tid];
        te1[tid] = (float)(a / (1.0 + exp(-a)));
    }
    __syncthreads();
    {
        double a = (double)b2[tid];
        for (int k = 0; k < 512; k++) a += (double)te1[k] * (double)w2[k * 512 + tid];
        te2[tid] = (float)(a / (1.0 + exp(-a)));
    }
    __syncthreads();
    if (tid < 192) {
        int l = tid >> 5, c = tid & 31;
        double a = (double)bt[l * 32 + c];
        for (int k = 0; k < 512; k++) a += (double)te2[k] * (double)wt[(l * 512 + k) * 32 + c];
        g_cond[(l * NSTEPS + t) * 32 + c] = (float)a;
    }
}

// Single conv body, runtime dilation (no 6x template replication).
__device__ __forceinline__ void conv_mma(const __half* hT_hi, const __half* hT_lo,
                                         __half* aT_hi, __half* aT_lo,
                                         const float* __restrict__ bdil,
                                         int l, int dil, int w, int lane) {
    const int frow = lane >> 2, fcol = 2 * (lane & 3);
    float bg = bdil[l * 64 + 8 * w + frow], bf = bdil[l * 64 + 32 + 8 * w + frow];
    float acc[3][4];
#pragma unroll
    for (int n = 0; n < 3; n++) { acc[n][0] = bg; acc[n][1] = bg; acc[n][2] = bf; acc[n][3] = bf; }
#pragma unroll
    for (int tp = 0; tp < 3; tp++)
#pragma unroll
        for (int kt = 0; kt < 2; kt++) {
            int base = ((((l * 3 + tp) * 2 + kt) * 2) * 4 + w) * 32 + lane;
            uint4 Ah = g_wA[base], Al = g_wA[base + 128];
            mma3x3(acc, Ah, Al, hT_hi, hT_lo,
                   32 + frow + (tp - 1) * dil, 8, kt * 16 + fcol);
        }
    int o = 8 * w + frow;
#pragma unroll
    for (int n = 0; n < 3; n++) {
        int j = n * 8 + fcol;
        wsplit(aT_hi, aT_lo, j * HT + o, tanh_hw(acc[n][2]) * sigm_hw(acc[n][0]));
        wsplit(aT_hi, aT_lo, (j + 1) * HT + o, tanh_hw(acc[n][3]) * sigm_hw(acc[n][1]));
    }
}

__global__ __launch_bounds__(128, 4) void k_main(
    const float* __restrict__ z_init, const float* __restrict__ noise,
    const float* __restrict__ b_in, const float* __restrict__ bdil,
    const float* __restrict__ bout, const float* __restrict__ b_o1,
    const float* __restrict__ b_o2, float* __restrict__ out) {
    extern __shared__ __align__(16) char dyn[];
    __half* hT_hi = (__half*)dyn;
    __half* hT_lo = (__half*)(dyn + 7040);
    __half* aT_hi = (__half*)(dyn + 14080);
    __half* aT_lo = (__half*)(dyn + 16000);
    __half* skT_hi = (__half*)(dyn + 17920);
    __half* skT_lo = (__half*)(dyn + 19840);
    __half* xT_hi = (__half*)(dyn + 21760);
    __half* xT_lo = (__half*)(dyn + 28288);
    float* nzS = (float*)(dyn + 34816);   // 12288 -> 47104

    const int tid = threadIdx.x, chain = blockIdx.x;
    const int lane = tid & 31, warp = tid >> 5;
    const int frow = lane >> 2, fcol = 2 * (lane & 3);
    const unsigned nz_dst = (unsigned)__cvta_generic_to_shared(&nzS[tid * 24]);

    {
        const float4* zp = (const float4*)(z_init + (size_t)chain * 3072);
#pragma unroll
        for (int q = 0; q < 6; q++) {
            float4 v = zp[tid * 6 + q];
            int j = 4 * q;
            wsplit(xT_hi, xT_lo, j * XT + tid, v.x);
            wsplit(xT_hi, xT_lo, (j + 1) * XT + tid, v.y);
            wsplit(xT_hi, xT_lo, (j + 2) * XT + tid, v.z);
            wsplit(xT_hi, xT_lo, (j + 3) * XT + tid, v.w);
        }
    }
    for (int i = tid; i < 88 * HT / 2; i += 128) { ((u32*)hT_hi)[i] = 0u; ((u32*)hT_lo)[i] = 0u; }
    __syncthreads();

    float fR[3][4];

    for (int t = NSTEPS - 1; t >= 0; t--) {
        const float s1m = g_coef[t * 5], isab = g_coef[t * 5 + 1];
        const float c0 = g_coef[t * 5 + 2], cxt = g_coef[t * 5 + 3], sg = g_coef[t * 5 + 4];
        {
            const float* nsrc = noise + ((size_t)(NSTEPS - 1 - t) * 512 + chain) * 3072 + (size_t)tid * 24;
#pragma unroll
            for (int q = 0; q < 6; q++) cpasync16(nz_dst + 16 * q, nsrc + 4 * q);
            asm volatile("cp.async.commit_group;");
        }
        // A: h = relu(W_in @ x + b), warps 0-1 (fragments = res-warp h state)
        if (warp < 2) {
            int c = 16 * warp + frow;
            float b0 = b_in[c], b8 = b_in[c + 8];
            float cn0 = g_cond[t * 32 + c], cn8 = g_cond[t * 32 + c + 8];
            float acc[3][4];
#pragma unroll
            for (int n = 0; n < 3; n++) { acc[n][0] = b0; acc[n][1] = b0; acc[n][2] = b8; acc[n][3] = b8; }
#pragma unroll
            for (int kc = 0; kc < 8; kc++) {
                int base = ((kc * 2) * 2 + warp) * 32 + lane;
                uint4 Ah = g_wIn[base], Al = g_wIn[base + 64];
                u32 bh0[3], bh1[3], bl0[3], bl1[3];
#pragma unroll
                for (int n = 0; n < 3; n++) {
                    int coff = (n * 8 + frow) * XT + kc * 16 + fcol;
                    bh0[n] = *(const u32*)&xT_hi[coff]; bh1[n] = *(const u32*)&xT_hi[coff + 8];
                    bl0[n] = *(const u32*)&xT_lo[coff]; bl1[n] = *(const u32*)&xT_lo[coff + 8];
                }
#pragma unroll
                for (int n = 0; n < 3; n++) mma16816(acc[n], Ah, bh0[n], bh1[n]);
#pragma unroll
                for (int n = 0; n < 3; n++) mma16816(acc[n], Ah, bl0[n], bl1[n]);
#pragma unroll
                for (int n = 0; n < 3; n++) mma16816(acc[n], Al, bh0[n], bh1[n]);
            }
#pragma unroll
            for (int n = 0; n < 3; n++) {
                int j = n * 8 + fcol;
#pragma unroll
                for (int q = 0; q < 4; q++) fR[n][q] = fmaxf(acc[n][q], 0.f);
                wsplit(hT_hi, hT_lo, (32 + j) * HT + c, fR[n][0] + cn0);
                wsplit(hT_hi, hT_lo, (33 + j) * HT + c, fR[n][1] + cn0);
                wsplit(hT_hi, hT_lo, (32 + j) * HT + c + 8, fR[n][2] + cn8);
                wsplit(hT_hi, hT_lo, (33 + j) * HT + c + 8, fR[n][3] + cn8);
            }
        } else {
#pragma unroll
            for (int n = 0; n < 3; n++) { fR[n][0] = 0.f; fR[n][1] = 0.f; fR[n][2] = 0.f; fR[n][3] = 0.f; }
        }
        __syncthreads();

        int dil = 1;
        for (int l = 0; l < 6; l++, dil <<= 1) {
            conv_mma(hT_hi, hT_lo, aT_hi, aT_lo, bdil, l, dil, warp, lane);
            __syncthreads();
            {
                bool resw = (warp < 2);
                if (resw ? (l < 5) : true) {
                    int c = resw ? 16 * warp + frow : 16 * (warp - 2) + frow;
                    int ob = resw ? c : 32 + c;
                    float b0 = bout[l * 64 + ob], b8 = bout[l * 64 + ob + 8];
                    float acc[3][4];
#pragma unroll
                    for (int n = 0; n < 3; n++) { acc[n][0] = b0; acc[n][1] = b0; acc[n][2] = b8; acc[n][3] = b8; }
#pragma unroll
                    for (int kt = 0; kt < 2; kt++) {
                        int base = (((l * 2 + kt) * 2) * 4 + warp) * 32 + lane;
                        uint4 Ah = g_wE[base], Al = g_wE[base + 128];
                        mma3x3(acc, Ah, Al, aT_hi, aT_lo, frow, 8, kt * 16 + fcol);
                    }
                    if (resw) {
                        float cn0 = g_cond[((l + 1) * NSTEPS + t) * 32 + c];
                        float cn8 = g_cond[((l + 1) * NSTEPS + t) * 32 + c + 8];
#pragma unroll
                        for (int n = 0; n < 3; n++) {
                            int j = n * 8 + fcol;
#pragma unroll
                            for (int q = 0; q < 4; q++)
                                fR[n][q] = (fR[n][q] + acc[n][q]) * 0.70710678118654752f;
                            wsplit(hT_hi, hT_lo, (32 + j) * HT + c, fR[n][0] + cn0);
                            wsplit(hT_hi, hT_lo, (33 + j) * HT + c, fR[n][1] + cn0);
                            wsplit(hT_hi, hT_lo, (32 + j) * HT + c + 8, fR[n][2] + cn8);
                            wsplit(hT_hi, hT_lo, (33 + j) * HT + c + 8, fR[n][3] + cn8);
                        }
                    } else {
#pragma unroll
                        for (int n = 0; n < 3; n++) {
#pragma unroll
                            for (int q = 0; q < 4; q++) fR[n][q] += acc[n][q];
                        }
                        if (l == 5) {
#pragma unroll
                            for (int n = 0; n < 3; n++) {
                                int j = n * 8 + fcol;
                                wsplit(skT_hi, skT_lo, j * HT + c, fR[n][0]);
                                wsplit(skT_hi, skT_lo, (j + 1) * HT + c, fR[n][1]);
                                wsplit(skT_hi, skT_lo, j * HT + c + 8, fR[n][2]);
                                wsplit(skT_hi, skT_lo, (j + 1) * HT + c + 8, fR[n][3]);
                            }
                        }
                    }
                }
            }
            __syncthreads();
        }
        // F: s = relu(W_o1 @ skip/sqrt6 + b), warps 0-1 -> aT
        if (warp < 2) {
            int c = 16 * warp + frow;
            float b0 = b_o1[c], b8 = b_o1[c + 8];
            float acc[3][4];
#pragma unroll
            for (int n = 0; n < 3; n++) { acc[n][0] = b0; acc[n][1] = b0; acc[n][2] = b8; acc[n][3] = b8; }
#pragma unroll
            for (int kt = 0; kt < 2; kt++) {
                int base = ((kt * 2) * 2 + warp) * 32 + lane;
                uint4 Ah = g_wF[base], Al = g_wF[base + 64];
                mma3x3(acc, Ah, Al, skT_hi, skT_lo, frow, 8, kt * 16 + fcol);
            }
#pragma unroll
            for (int n = 0; n < 3; n++) {
                int j = n * 8 + fcol;
                wsplit(aT_hi, aT_lo, j * HT + c, fmaxf(acc[n][0], 0.f));
                wsplit(aT_hi, aT_lo, (j + 1) * HT + c, fmaxf(acc[n][1], 0.f));
                wsplit(aT_hi, aT_lo, j * HT + c + 8, fmaxf(acc[n][2], 0.f));
                wsplit(aT_hi, aT_lo, (j + 1) * HT + c + 8, fmaxf(acc[n][3], 0.f));
            }
        }
        __syncthreads();
        // G: eps = W_o2 @ s (all warps, 2 m-tiles); DDPM update of split-x
#pragma unroll
        for (int m = 0; m < 2; m++) {
            int mt8 = 2 * warp + m, dbase = 16 * mt8;
            float b0 = b_o2[dbase + frow], b8 = b_o2[dbase + frow + 8];
            float acc[3][4];
#pragma unroll
            for (int n = 0; n < 3; n++) { acc[n][0] = b0; acc[n][1] = b0; acc[n][2] = b8; acc[n][3] = b8; }
#pragma unroll
            for (int kt = 0; kt < 2; kt++) {
                int base = ((kt * 2) * 8 + mt8) * 32 + lane;
                uint4 Ah = g_wG[base], Al = g_wG[base + 256];
                mma3x3(acc, Ah, Al, aT_hi, aT_lo, frow, 8, kt * 16 + fcol);
            }
            if (m == 0) asm volatile("cp.async.wait_group 0;" ::: "memory");
#pragma unroll
            for (int n = 0; n < 3; n++)
#pragma unroll
                for (int r = 0; r < 2; r++) {
                    int d = dbase + frow + 8 * r;
                    int j = n * 8 + fcol;
                    float2 nz = *(const float2*)&nzS[d * 24 + j];
#pragma unroll
                    for (int e = 0; e < 2; e++) {
                        int xa = (j + e) * XT + d;
                        float x = __half2float(xT_hi[xa]) + __half2float(xT_lo[xa]);
                        float eps = acc[n][2 * r + e];
                        float x0 = fminf(fmaxf((x - s1m * eps) * isab, -1.f), 1.f);
                        float xn = fmaf(c0, x0, fmaf(cxt, x, sg * (e ? nz.y : nz.x)));
                        wsplit(xT_hi, xT_lo, xa, xn);
                    }
                }
        }
        __syncthreads();
    }
    {
        int b = chain & 31;
        float lc = g_loc[b * 128 + tid];
        float scl = g_scale[b * 128 + tid];
        for (int hh = 0; hh < 24; hh++) {
            int xa = hh * XT + tid;
            double z = (double)(__half2float(xT_hi[xa]) + __half2float(xT_lo[xa]));
            double u = 0.5 * erfc(-z * 0.70710678118654752440);
            u = fmin(fmax(u, 1e-6), 1.0 - 1e-6);
            double a = 4.0 * u * (1.0 - u);
            a = fmin(fmax(a, 1e-12), 1.0);
            double r = sqrt(a);
            double q = 2.0 * sqrt(fmax(cos(acos(r) / 3.0) / r - 1.0, 0.0));
            double sgn = (u >= 0.5) ? 1.0 : -1.0;
            out[((size_t)chain * 24 + hh) * 128 + tid] = (float)((double)lc + (double)scl * sgn * q);
        }
    }
}

extern "C" void kernel_launch(void* const* d_in, const int* in_sizes, int n_in,
                              void* d_out, int out_size) {
    const float* x_hist = (const float*)d_in[0];
    const float* z_init = (const float*)d_in[1];
    const float* noise = (const float*)d_in[2];
    const float* w_in = (const float*)d_in[3];
    const float* b_in = (const float*)d_in[4];
    const float* tw1 = (const float*)d_in[5];
    const float* tb1 = (const float*)d_in[6];
    const float* tw2 = (const float*)d_in[7];
    const float* tb2 = (const float*)d_in[8];
    const float* lwt = (const float*)d_in[9];
    const float* lbt = (const float*)d_in[10];
    const float* lwd = (const float*)d_in[11];
    const float* lbd = (const float*)d_in[12];
    const float* lwo = (const float*)d_in[13];
    const float* lbo = (const float*)d_in[14];
    const float* w_o1 = (const float*)d_in[15];
    const float* b_o1 = (const float*)d_in[16];
    const float* w_o2 = (const float*)d_in[17];
    const float* b_o2 = (const float*)d_in[18];
    float* out = (float*)d_out;

    const int SMEM = 47104;
    cudaFuncSetAttribute(k_main, cudaFuncAttributeMaxDynamicSharedMemorySize, SMEM);
    k_prep<<<64, 256>>>(w_in, lwd, lwo, w_o1, w_o2);
    k_stats<<<32, 128>>>(x_hist);
    k_temb<<<50, 512>>>(tw1, tb1, tw2, tb2, lwt, lbt);
    k_main<<<512, 128, SMEM>>>(z_init, noise, b_in, lbd, lbo, b_o1, b_o2, out);
}

// round 16
// speedup vs baseline: 1.1936x; 1.0014x over previous
#include <cuda_runtime.h>
#include <cuda_fp16.h>
#include <math.h>

#define NSTEPS 50
#define HT 40
#define XT 136
typedef unsigned u32;

__device__ float g_loc[4096], g_scale[4096];
__device__ float g_cond[6 * NSTEPS * 32], g_coef[NSTEPS * 5];
__device__ uint4 g_wA[6 * 3 * 2 * 2 * 4 * 32];
__device__ uint4 g_wE[6 * 2 * 2 * 4 * 32];
__device__ uint4 g_wIn[8 * 2 * 2 * 32];
__device__ uint4 g_wF[2 * 2 * 2 * 32];
__device__ uint4 g_wG[2 * 2 * 8 * 32];

__device__ __forceinline__ float tanh_hw(float x) {
    float y; asm("tanh.approx.f32 %0, %1;" : "=f"(y) : "f"(x)); return y;
}
__device__ __forceinline__ float sigm_hw(float x) {
    return fmaf(0.5f, tanh_hw(0.5f * x), 0.5f);
}
__device__ __forceinline__ void cpasync16(unsigned dst, const void* src) {
    asm volatile("cp.async.ca.shared.global [%0], [%1], 16;" :: "r"(dst), "l"(src));
}
__device__ __forceinline__ void mma16816(float c[4], const uint4& a, u32 b0, u32 b1) {
    asm("mma.sync.aligned.m16n8k16.row.col.f32.f16.f16.f32 "
        "{%0,%1,%2,%3}, {%4,%5,%6,%7}, {%8,%9}, {%0,%1,%2,%3};"
        : "+f"(c[0]), "+f"(c[1]), "+f"(c[2]), "+f"(c[3])
        : "r"(a.x), "r"(a.y), "r"(a.z), "r"(a.w), "r"(b0), "r"(b1));
}
__device__ __forceinline__ void wsplit(__half* hb, __half* lb, int idx, float v) {
    __half h = __float2half_rn(v);
    hb[idx] = h;
    lb[idx] = __float2half_rn(v - __half2float(h));
}
__device__ __forceinline__ u32 encpair(float w0, float w1, int var) {
    __half h0 = __float2half_rn(w0), h1 = __float2half_rn(w1);
    if (var) {
        h0 = __float2half_rn(w0 - __half2float(h0));
        h1 = __float2half_rn(w1 - __half2float(h1));
    }
    return (u32)__half_as_ushort(h0) | ((u32)__half_as_ushort(h1) << 16);
}
// 3 n-tiles, grouped by term (AhBh x3, AhBl x3, AlBh x3), single accumulator set.
__device__ __forceinline__ void mma3x3(float acc[3][4], const uint4& Ah, const uint4& Al,
                                       const __half* bhi, const __half* blo,
                                       int r0, int rs, int coff) {
    u32 bh0[3], bh1[3], bl0[3], bl1[3];
#pragma unroll
    for (int n = 0; n < 3; n++) {
        int c = (r0 + n * rs) * HT + coff;
        bh0[n] = *(const u32*)&bhi[c]; bh1[n] = *(const u32*)&bhi[c + 8];
        bl0[n] = *(const u32*)&blo[c]; bl1[n] = *(const u32*)&blo[c + 8];
    }
#pragma unroll
    for (int n = 0; n < 3; n++) mma16816(acc[n], Ah, bh0[n], bh1[n]);
#pragma unroll
    for (int n = 0; n < 3; n++) mma16816(acc[n], Ah, bl0[n], bl1[n]);
#pragma unroll
    for (int n = 0; n < 3; n++) mma16816(acc[n], Al, bh0[n], bh1[n]);
}

__global__ void k_prep(const float* __restrict__ w_in, const float* __restrict__ lwd,
                       const float* __restrict__ lwo, const float* __restrict__ w_o1,
                       const float* __restrict__ w_o2) {
    int i = blockIdx.x * blockDim.x + threadIdx.x;
    int nt = gridDim.x * blockDim.x;
    for (int idx = i; idx < 6 * 3 * 2 * 2 * 4 * 32; idx += nt) {
        int lane = idx & 31, r = idx >> 5;
        int mt = r & 3; r >>= 2;
        int var = r & 1; r >>= 1;
        int kt = r & 1; r >>= 1;
        int tp = r % 3, l = r / 3;
        int og = 8 * mt + (lane >> 2), of = 32 + 8 * mt + (lane >> 2);
        int cb = kt * 16 + 2 * (lane & 3);
        auto w = [&](int o, int c) { return lwd[((l * 64 + o) * 32 + c) * 3 + tp]; };
        uint4 v;
        v.x = encpair(w(og, cb), w(og, cb + 1), var);
        v.y = encpair(w(of, cb), w(of, cb + 1), var);
        v.z = encpair(w(og, cb + 8), w(og, cb + 9), var);
        v.w = encpair(w(of, cb + 8), w(of, cb + 9), var);
        g_wA[idx] = v;
    }
    for (int idx = i; idx < 6 * 2 * 2 * 4 * 32; idx += nt) {
        int lane = idx & 31, r = idx >> 5;
        int mt = r & 3; r >>= 2;
        int var = r & 1; r >>= 1;
        int kt = r & 1; r >>= 1;
        int l = r;
        int o = 16 * mt + (lane >> 2);
        int cb = kt * 16 + 2 * (lane & 3);
        auto w = [&](int oo, int c) { return lwo[(l * 64 + oo) * 32 + c]; };
        uint4 v;
        v.x = encpair(w(o, cb), w(o, cb + 1), var);
        v.y = encpair(w(o + 8, cb), w(o + 8, cb + 1), var);
        v.z = encpair(w(o, cb + 8), w(o, cb + 9), var);
        v.w = encpair(w(o + 8, cb + 8), w(o + 8, cb + 9), var);
        g_wE[idx] = v;
    }
    for (int idx = i; idx < 8 * 2 * 2 * 32; idx += nt) {
        int lane = idx & 31, r = idx >> 5;
        int mt = r & 1; r >>= 1;
        int var = r & 1; r >>= 1;
        int kc = r;
        int o = 16 * mt + (lane >> 2);
        int cb = kc * 16 + 2 * (lane & 3);
        auto w = [&](int oo, int d) { return w_in[oo * 128 + d]; };
        uint4 v;
        v.x = encpair(w(o, cb), w(o, cb + 1), var);
        v.y = encpair(w(o + 8, cb), w(o + 8, cb + 1), var);
        v.z = encpair(w(o, cb + 8), w(o, cb + 9), var);
        v.w = encpair(w(o + 8, cb + 8), w(o + 8, cb + 9), var);
        g_wIn[idx] = v;
    }
    for (int idx = i; idx < 2 * 2 * 2 * 32; idx += nt) {
        int lane = idx & 31, r = idx >> 5;
        int mt = r & 1; r >>= 1;
        int var = r & 1; r >>= 1;
        int kt = r;
        int o = 16 * mt + (lane >> 2);
        int cb = kt * 16 + 2 * (lane & 3);
        const float s = 0.40824829046386302f;
        auto w = [&](int oo, int c) { return w_o1[oo * 32 + c] * s; };
        uint4 v;
        v.x = encpair(w(o, cb), w(o, cb + 1), var);
        v.y = encpair(w(o + 8, cb), w(o + 8, cb + 1), var);
        v.z = encpair(w(o, cb + 8), w(o, cb + 9), var);
        v.w = encpair(w(o + 8, cb + 8), w(o + 8, cb + 9), var);
        g_wF[idx] = v;
    }
    for (int idx = i; idx < 2 * 2 * 8 * 32; idx += nt) {
        int lane = idx & 31, r = idx >> 5;
        int mt8 = r & 7; r >>= 3;
        int var = r & 1; r >>= 1;
        int kt = r;
        int o = 16 * mt8 + (lane >> 2);
        int cb = kt * 16 + 2 * (lane & 3);
        auto w = [&](int oo, int c) { return w_o2[oo * 32 + c]; };
        uint4 v;
        v.x = encpair(w(o, cb), w(o, cb + 1), var);
        v.y = encpair(w(o + 8, cb), w(o + 8, cb + 1), var);
        v.z = encpair(w(o, cb + 8), w(o, cb + 9), var);
        v.w = encpair(w(o + 8, cb + 8), w(o + 8, cb + 9), var);
        g_wG[idx] = v;
    }
    if (i == 0) {
        double abar = 1.0;
        for (int t = 0; t < NSTEPS; t++) {
            double beta = 1e-4 + (double)t * (0.1 - 1e-4) / 49.0;
            double alpha = 1.0 - beta, abp = abar;
            abar *= alpha;
            double om = 1.0 - abar;
            g_coef[t * 5 + 0] = (float)sqrt(om);
            g_coef[t * 5 + 1] = (float)(1.0 / sqrt(abar));
            g_coef[t * 5 + 2] = (float)(beta * sqrt(abp) / om);
            g_coef[t * 5 + 3] = (float)((1.0 - abp) * sqrt(alpha) / om);
            double pv = beta * (1.0 - abp) / om;
            g_coef[t * 5 + 4] = (t > 0) ? (float)sqrt(pv) : 0.0f;
        }
    }
}

__global__ void k_stats(const float* __restrict__ x_hist) {
    int b = blockIdx.x, d = threadIdx.x;
    const float* xb = x_hist + (size_t)b * 192 * 128 + d;
    double s = 0.0;
    for (int t = 0; t < 192; t++) s += (double)xb[t * 128];
    float mean = (float)(s / 192.0);
    float c = xb[0] - mean;
    float v = c * c;
    for (int t = 1; t < 192; t++) {
        float cc = xb[t * 128] - mean;
        v = 0.94f * v + 0.06f * (cc * cc);
    }
    g_loc[b * 128 + d] = mean;
    g_scale[b * 128 + d] = fmaxf(sqrtf(v * 0.5f), 1e-5f);
}

__global__ void k_temb(const float* __restrict__ w1, const float* __restrict__ b1,
                       const float* __restrict__ w2, const float* __restrict__ b2,
                       const float* __restrict__ wt, const float* __restrict__ bt) {
    __shared__ float pe[128], te1[512], te2[512];
    int t = blockIdx.x, tid = threadIdx.x;
    if (tid < 64) {
        float y = ((float)tid * 4.0f) / 63.0f;
        float p = (float)pow(10.0, (double)y);
        float e = (float)t * p;
        pe[tid] = (float)sin((double)e);
        pe[tid + 64] = (float)cos((double)e);
    }
    __syncthreads();
    {
        double a = (double)b1[tid];
        for (int j = 0; j < 128; j++) a += (double)pe[j] * (double)w1[j * 512 + tid];
        te1[tid] = (float)(a / (1.0 + exp(-a)));
    }
    __syncthreads();
    {
        double a = (double)b2[tid];
        for (int k = 0; k < 512; k++) a += (double)te1[k] * (double)w2[k * 512 + tid];
        te2[tid] = (float)(a / (1.0 + exp(-a)));
    }
    __syncthreads();
    if (tid < 192) {
        int l = tid >> 5, c = tid & 31;
        double a = (double)bt[l * 32 + c];
        for (int k = 0; k < 512; k++) a += (double)te2[k] * (double)wt[(l * 512 + k) * 32 + c];
        g_cond[(l * NSTEPS + t) * 32 + c] = (float)a;
    }
}

// Single conv body, runtime dilation (no 6x template replication).
__device__ __forceinline__ void conv_mma(const __half* hT_hi, const __half* hT_lo,
                                         __half* aT_hi, __half* aT_lo,
                                         const float* __restrict__ bdil,
                                         int l, int dil, int w, int lane) {
    const int frow = lane >> 2, fcol = 2 * (lane & 3);
    float bg = bdil[l * 64 + 8 * w + frow], bf = bdil[l * 64 + 32 + 8 * w + frow];
    float acc[3][4];
#pragma unroll
    for (int n = 0; n < 3; n++) { acc[n][0] = bg; acc[n][1] = bg; acc[n][2] = bf; acc[n][3] = bf; }
#pragma unroll
    for (int tp = 0; tp < 3; tp++)
#pragma unroll
        for (int kt = 0; kt < 2; kt++) {
            int base = ((((l * 3 + tp) * 2 + kt) * 2) * 4 + w) * 32 + lane;
            uint4 Ah = g_wA[base], Al = g_wA[base + 128];
            mma3x3(acc, Ah, Al, hT_hi, hT_lo,
                   32 + frow + (tp - 1) * dil, 8, kt * 16 + fcol);
        }
    int o = 8 * w + frow;
#pragma unroll
    for (int n = 0; n < 3; n++) {
        int j = n * 8 + fcol;
        wsplit(aT_hi, aT_lo, j * HT + o, tanh_hw(acc[n][2]) * sigm_hw(acc[n][0]));
        wsplit(aT_hi, aT_lo, (j + 1) * HT + o, tanh_hw(acc[n][3]) * sigm_hw(acc[n][1]));
    }
}

__global__ __launch_bounds__(128, 4) void k_main(
    const float* __restrict__ z_init, const float* __restrict__ noise,
    const float* __restrict__ b_in, const float* __restrict__ bdil,
    const float* __restrict__ bout, const float* __restrict__ b_o1,
    const float* __restrict__ b_o2, float* __restrict__ out) {
    extern __shared__ __align__(16) char dyn[];
    __half* hT_hi = (__half*)dyn;
    __half* hT_lo = (__half*)(dyn + 7040);
    __half* aT_hi = (__half*)(dyn + 14080);
    __half* aT_lo = (__half*)(dyn + 16000);
    __half* skT_hi = (__half*)(dyn + 17920);
    __half* skT_lo = (__half*)(dyn + 19840);
    __half* xT_hi = (__half*)(dyn + 21760);
    __half* xT_lo = (__half*)(dyn + 28288);
    float* nzS = (float*)(dyn + 34816);   // 12288 -> 47104

    const int tid = threadIdx.x, chain = blockIdx.x;
    const int lane = tid & 31, warp = tid >> 5;
    const int frow = lane >> 2, fcol = 2 * (lane & 3);
    const unsigned nz_dst = (unsigned)__cvta_generic_to_shared(&nzS[tid * 24]);

    {
        const float4* zp = (const float4*)(z_init + (size_t)chain * 3072);
#pragma unroll
        for (int q = 0; q < 6; q++) {
            float4 v = zp[tid * 6 + q];
            int j = 4 * q;
            wsplit(xT_hi, xT_lo, j * XT + tid, v.x);
            wsplit(xT_hi, xT_lo, (j + 1) * XT + tid, v.y);
            wsplit(xT_hi, xT_lo, (j + 2) * XT + tid, v.z);
            wsplit(xT_hi, xT_lo, (j + 3) * XT + tid, v.w);
        }
    }
    for (int i = tid; i < 88 * HT / 2; i += 128) { ((u32*)hT_hi)[i] = 0u; ((u32*)hT_lo)[i] = 0u; }
    __syncthreads();

    float fR[3][4];

    for (int t = NSTEPS - 1; t >= 0; t--) {
        const float s1m = g_coef[t * 5], isab = g_coef[t * 5 + 1];
        const float c0 = g_coef[t * 5 + 2], cxt = g_coef[t * 5 + 3], sg = g_coef[t * 5 + 4];
        {
            const float* nsrc = noise + ((size_t)(NSTEPS - 1 - t) * 512 + chain) * 3072 + (size_t)tid * 24;
#pragma unroll
            for (int q = 0; q < 6; q++) cpasync16(nz_dst + 16 * q, nsrc + 4 * q);
            asm volatile("cp.async.commit_group;");
        }
        // A: h = relu(W_in @ x + b), warps 0-1 (fragments = res-warp h state)
        if (warp < 2) {
            int c = 16 * warp + frow;
            float b0 = b_in[c], b8 = b_in[c + 8];
            float cn0 = g_cond[t * 32 + c], cn8 = g_cond[t * 32 + c + 8];
            float acc[3][4];
#pragma unroll
            for (int n = 0; n < 3; n++) { acc[n][0] = b0; acc[n][1] = b0; acc[n][2] = b8; acc[n][3] = b8; }
#pragma unroll
            for (int kc = 0; kc < 8; kc++) {
                int base = ((kc * 2) * 2 + warp) * 32 + lane;
                uint4 Ah = g_wIn[base], Al = g_wIn[base + 64];
                u32 bh0[3], bh1[3], bl0[3], bl1[3];
#pragma unroll
                for (int n = 0; n < 3; n++) {
                    int coff = (n * 8 + frow) * XT + kc * 16 + fcol;
                    bh0[n] = *(const u32*)&xT_hi[coff]; bh1[n] = *(const u32*)&xT_hi[coff + 8];
                    bl0[n] = *(const u32*)&xT_lo[coff]; bl1[n] = *(const u32*)&xT_lo[coff + 8];
                }
#pragma unroll
                for (int n = 0; n < 3; n++) mma16816(acc[n], Ah, bh0[n], bh1[n]);
#pragma unroll
                for (int n = 0; n < 3; n++) mma16816(acc[n], Ah, bl0[n], bl1[n]);
#pragma unroll
                for (int n = 0; n < 3; n++) mma16816(acc[n], Al, bh0[n], bh1[n]);
            }
#pragma unroll
            for (int n = 0; n < 3; n++) {
                int j = n * 8 + fcol;
#pragma unroll
                for (int q = 0; q < 4; q++) fR[n][q] = fmaxf(acc[n][q], 0.f);
                wsplit(hT_hi, hT_lo, (32 + j) * HT + c, fR[n][0] + cn0);
                wsplit(hT_hi, hT_lo, (33 + j) * HT + c, fR[n][1] + cn0);
                wsplit(hT_hi, hT_lo, (32 + j) * HT + c + 8, fR[n][2] + cn8);
                wsplit(hT_hi, hT_lo, (33 + j) * HT + c + 8, fR[n][3] + cn8);
            }
        } else {
#pragma unroll
            for (int n = 0; n < 3; n++) { fR[n][0] = 0.f; fR[n][1] = 0.f; fR[n][2] = 0.f; fR[n][3] = 0.f; }
        }
        __syncthreads();

        int dil = 1;
        for (int l = 0; l < 6; l++, dil <<= 1) {
            conv_mma(hT_hi, hT_lo, aT_hi, aT_lo, bdil, l, dil, warp, lane);
            __syncthreads();
            {
                bool resw = (warp < 2);
                if (resw ? (l < 5) : true) {
                    int c = resw ? 16 * warp + frow : 16 * (warp - 2) + frow;
                    int ob = resw ? c : 32 + c;
                    float b0 = bout[l * 64 + ob], b8 = bout[l * 64 + ob + 8];
                    float acc[3][4];
#pragma unroll
                    for (int n = 0; n < 3; n++) { acc[n][0] = b0; acc[n][1] = b0; acc[n][2] = b8; acc[n][3] = b8; }
#pragma unroll
                    for (int kt = 0; kt < 2; kt++) {
                        int base = (((l * 2 + kt) * 2) * 4 + warp) * 32 + lane;
                        uint4 Ah = g_wE[base], Al = g_wE[base + 128];
                        mma3x3(acc, Ah, Al, aT_hi, aT_lo, frow, 8, kt * 16 + fcol);
                    }
                    if (resw) {
                        float cn0 = g_cond[((l + 1) * NSTEPS + t) * 32 + c];
                        float cn8 = g_cond[((l + 1) * NSTEPS + t) * 32 + c + 8];
#pragma unroll
                        for (int n = 0; n < 3; n++) {
                            int j = n * 8 + fcol;
#pragma unroll
                            for (int q = 0; q < 4; q++)
                                fR[n][q] = (fR[n][q] + acc[n][q]) * 0.70710678118654752f;
                            wsplit(hT_hi, hT_lo, (32 + j) * HT + c, fR[n][0] + cn0);
                            wsplit(hT_hi, hT_lo, (33 + j) * HT + c, fR[n][1] + cn0);
                            wsplit(hT_hi, hT_lo, (32 + j) * HT + c + 8, fR[n][2] + cn8);
                            wsplit(hT_hi, hT_lo, (33 + j) * HT + c + 8, fR[n][3] + cn8);
                        }
                    } else {
#pragma unroll
                        for (int n = 0; n < 3; n++) {
#pragma unroll
                            for (int q = 0; q < 4; q++) fR[n][q] += acc[n][q];
                        }
                        if (l == 5) {
#pragma unroll
                            for (int n = 0; n < 3; n++) {
                                int j = n * 8 + fcol;
                                wsplit(skT_hi, skT_lo, j * HT + c, fR[n][0]);
                                wsplit(skT_hi, skT_lo, (j + 1) * HT + c, fR[n][1]);
                                wsplit(skT_hi, skT_lo, j * HT + c + 8, fR[n][2]);
                                wsplit(skT_hi, skT_lo, (j + 1) * HT + c + 8, fR[n][3]);
                            }
                        }
                    }
                }
            }
            __syncthreads();
        }
        // F: s = relu(W_o1 @ skip/sqrt6 + b), warps 0-1 -> aT
        if (warp < 2) {
            int c = 16 * warp + frow;
            float b0 = b_o1[c], b8 = b_o1[c + 8];
            float acc[3][4];
#pragma unroll
            for (int n = 0; n < 3; n++) { acc[n][0] = b0; acc[n][1] = b0; acc[n][2] = b8; acc[n][3] = b8; }
#pragma unroll
            for (int kt = 0; kt < 2; kt++) {
                int base = ((kt * 2) * 2 + warp) * 32 + lane;
                uint4 Ah = g_wF[base], Al = g_wF[base + 64];
                mma3x3(acc, Ah, Al, skT_hi, skT_lo, frow, 8, kt * 16 + fcol);
            }
#pragma unroll
            for (int n = 0; n < 3; n++) {
                int j = n * 8 + fcol;
                wsplit(aT_hi, aT_lo, j * HT + c, fmaxf(acc[n][0], 0.f));
                wsplit(aT_hi, aT_lo, (j + 1) * HT + c, fmaxf(acc[n][1], 0.f));
                wsplit(aT_hi, aT_lo, j * HT + c + 8, fmaxf(acc[n][2], 0.f));
                wsplit(aT_hi, aT_lo, (j + 1) * HT + c + 8, fmaxf(acc[n][3], 0.f));
            }
        }
        __syncthreads();
        // G: eps = W_o2 @ s (all warps, 2 m-tiles); DDPM update of split-x
#pragma unroll
        for (int m = 0; m < 2; m++) {
            int mt8 = 2 * warp + m, dbase = 16 * mt8;
            float b0 = b_o2[dbase + frow], b8 = b_o2[dbase + frow + 8];
            float acc[3][4];
#pragma unroll
            for (int n = 0; n < 3; n++) { acc[n][0] = b0; acc[n][1] = b0; acc[n][2] = b8; acc[n][3] = b8; }
#pragma unroll
            for (int kt = 0; kt < 2; kt++) {
                int base = ((kt * 2) * 8 + mt8) * 32 + lane;
                uint4 Ah = g_wG[base], Al = g_wG[base + 256];
                mma3x3(acc, Ah, Al, aT_hi, aT_lo, frow, 8, kt * 16 + fcol);
            }
            if (m == 0) asm volatile("cp.async.wait_group 0;" ::: "memory");
#pragma unroll
            for (int n = 0; n < 3; n++)
#pragma unroll
                for (int r = 0; r < 2; r++) {
                    int d = dbase + frow + 8 * r;
                    int j = n * 8 + fcol;
                    float2 nz = *(const float2*)&nzS[d * 24 + j];
#pragma unroll
                    for (int e = 0; e < 2; e++) {
                        int xa = (j + e) * XT + d;
                        float x = __half2float(xT_hi[xa]) + __half2float(xT_lo[xa]);
                        float eps = acc[n][2 * r + e];
                        float x0 = fminf(fmaxf((x - s1m * eps) * isab, -1.f), 1.f);
                        float xn = fmaf(c0, x0, fmaf(cxt, x, sg * (e ? nz.y : nz.x)));
                        wsplit(xT_hi, xT_lo, xa, xn);
                    }
                }
        }
        __syncthreads();
    }
    {
        int b = chain & 31;
        float lc = g_loc[b * 128 + tid];
        float scl = g_scale[b * 128 + tid];
        for (int hh = 0; hh < 24; hh++) {
            int xa = hh * XT + tid;
            double z = (double)(__half2float(xT_hi[xa]) + __half2float(xT_lo[xa]));
            double u = 0.5 * erfc(-z * 0.70710678118654752440);
            u = fmin(fmax(u, 1e-6), 1.0 - 1e-6);
            double a = 4.0 * u * (1.0 - u);
            a = fmin(fmax(a, 1e-12), 1.0);
            double r = sqrt(a);
            double q = 2.0 * sqrt(fmax(cos(acos(r) / 3.0) / r - 1.0, 0.0));
            double sgn = (u >= 0.5) ? 1.0 : -1.0;
            out[((size_t)chain * 24 + hh) * 128 + tid] = (float)((double)lc + (double)scl * sgn * q);
        }
    }
}

extern "C" void kernel_launch(void* const* d_in, const int* in_sizes, int n_in,
                              void* d_out, int out_size) {
    const float* x_hist = (const float*)d_in[0];
    const float* z_init = (const float*)d_in[1];
    const float* noise = (const float*)d_in[2];
    const float* w_in = (const float*)d_in[3];
    const float* b_in = (const float*)d_in[4];
    const float* tw1 = (const float*)d_in[5];
    const float* tb1 = (const float*)d_in[6];
    const float* tw2 = (const float*)d_in[7];
    const float* tb2 = (const float*)d_in[8];
    const float* lwt = (const float*)d_in[9];
    const float* lbt = (const float*)d_in[10];
    const float* lwd = (const float*)d_in[11];
    const float* lbd = (const float*)d_in[12];
    const float* lwo = (const float*)d_in[13];
    const float* lbo = (const float*)d_in[14];
    const float* w_o1 = (const float*)d_in[15];
    const float* b_o1 = (const float*)d_in[16];
    const float* w_o2 = (const float*)d_in[17];
    const float* b_o2 = (const float*)d_in[18];
    float* out = (float*)d_out;

    const int SMEM = 47104;
    cudaFuncSetAttribute(k_main, cudaFuncAttributeMaxDynamicSharedMemorySize, SMEM);
    k_prep<<<64, 256>>>(w_in, lwd, lwo, w_o1, w_o2);
    k_stats<<<32, 128>>>(x_hist);
    k_temb<<<50, 512>>>(tw1, tb1, tw2, tb2, lwt, lbt);
    k_main<<<512, 128, SMEM>>>(z_init, noise, b_in, lbd, lbo, b_o1, b_o2, out);
}

// round 17
// speedup vs baseline: 1.5402x; 1.2903x over previous
#include <cuda_runtime.h>
#include <cuda_fp16.h>
#include <math.h>

#define NSTEPS 50
#define HT 40
#define XT 136
typedef unsigned u32;

__device__ float g_loc[4096], g_scale[4096];
__device__ float g_cond[6 * NSTEPS * 32], g_coef[NSTEPS * 5];
__device__ uint4 g_wA[6 * 3 * 2 * 2 * 4 * 32];
__device__ uint4 g_wE[6 * 2 * 2 * 4 * 32];
__device__ uint4 g_wIn[8 * 2 * 2 * 32];
__device__ uint4 g_wF[2 * 2 * 2 * 32];
__device__ uint4 g_wG[2 * 2 * 8 * 32];

__device__ __forceinline__ float tanh_hw(float x) {
    float y; asm("tanh.approx.f32 %0, %1;" : "=f"(y) : "f"(x)); return y;
}
__device__ __forceinline__ float sigm_hw(float x) {
    return fmaf(0.5f, tanh_hw(0.5f * x), 0.5f);
}
__device__ __forceinline__ void cpasync16(unsigned dst, const void* src) {
    asm volatile("cp.async.ca.shared.global [%0], [%1], 16;" :: "r"(dst), "l"(src));
}
__device__ __forceinline__ void mma16816(float c[4], const uint4& a, u32 b0, u32 b1) {
    asm("mma.sync.aligned.m16n8k16.row.col.f32.f16.f16.f32 "
        "{%0,%1,%2,%3}, {%4,%5,%6,%7}, {%8,%9}, {%0,%1,%2,%3};"
        : "+f"(c[0]), "+f"(c[1]), "+f"(c[2]), "+f"(c[3])
        : "r"(a.x), "r"(a.y), "r"(a.z), "r"(a.w), "r"(b0), "r"(b1));
}
__device__ __forceinline__ void wsplit(__half* hb, __half* lb, int idx, float v) {
    __half h = __float2half_rn(v);
    hb[idx] = h;
    lb[idx] = __float2half_rn(v - __half2float(h));
}
__device__ __forceinline__ u32 encpair(float w0, float w1, int var) {
    __half h0 = __float2half_rn(w0), h1 = __float2half_rn(w1);
    if (var) {
        h0 = __float2half_rn(w0 - __half2float(h0));
        h1 = __float2half_rn(w1 - __half2float(h1));
    }
    return (u32)__half_as_ushort(h0) | ((u32)__half_as_ushort(h1) << 16);
}
// 3-term (hi/lo split) triple-n-tile MMA group.
__device__ __forceinline__ void mma3x3(float acc[3][4], const uint4& Ah, const uint4& Al,
                                       const __half* bhi, const __half* blo,
                                       int r0, int rs, int coff) {
    u32 bh0[3], bh1[3], bl0[3], bl1[3];
#pragma unroll
    for (int n = 0; n < 3; n++) {
        int c = (r0 + n * rs) * HT + coff;
        bh0[n] = *(const u32*)&bhi[c]; bh1[n] = *(const u32*)&bhi[c + 8];
        bl0[n] = *(const u32*)&blo[c]; bl1[n] = *(const u32*)&blo[c + 8];
    }
#pragma unroll
    for (int n = 0; n < 3; n++) mma16816(acc[n], Ah, bh0[n], bh1[n]);
#pragma unroll
    for (int n = 0; n < 3; n++) mma16816(acc[n], Ah, bl0[n], bl1[n]);
#pragma unroll
    for (int n = 0; n < 3; n++) mma16816(acc[n], Al, bh0[n], bh1[n]);
}

__global__ void k_prep(const float* __restrict__ w_in, const float* __restrict__ lwd,
                       const float* __restrict__ lwo, const float* __restrict__ w_o1,
                       const float* __restrict__ w_o2) {
    int i = blockIdx.x * blockDim.x + threadIdx.x;
    int nt = gridDim.x * blockDim.x;
    for (int idx = i; idx < 6 * 3 * 2 * 2 * 4 * 32; idx += nt) {
        int lane = idx & 31, r = idx >> 5;
        int mt = r & 3; r >>= 2;
        int var = r & 1; r >>= 1;
        int kt = r & 1; r >>= 1;
        int tp = r % 3, l = r / 3;
        int og = 8 * mt + (lane >> 2), of = 32 + 8 * mt + (lane >> 2);
        int cb = kt * 16 + 2 * (lane & 3);
        auto w = [&](int o, int c) { return lwd[((l * 64 + o) * 32 + c) * 3 + tp]; };
        uint4 v;
        v.x = encpair(w(og, cb), w(og, cb + 1), var);
        v.y = encpair(w(of, cb), w(of, cb + 1), var);
        v.z = encpair(w(og, cb + 8), w(og, cb + 9), var);
        v.w = encpair(w(of, cb + 8), w(of, cb + 9), var);
        g_wA[idx] = v;
    }
    for (int idx = i; idx < 6 * 2 * 2 * 4 * 32; idx += nt) {
        int lane = idx & 31, r = idx >> 5;
        int mt = r & 3; r >>= 2;
        int var = r & 1; r >>= 1;
        int kt = r & 1; r >>= 1;
        int l = r;
        int o = 16 * mt + (lane >> 2);
        int cb = kt * 16 + 2 * (lane & 3);
        auto w = [&](int oo, int c) { return lwo[(l * 64 + oo) * 32 + c]; };
        uint4 v;
        v.x = encpair(w(o, cb), w(o, cb + 1), var);
        v.y = encpair(w(o + 8, cb), w(o + 8, cb + 1), var);
        v.z = encpair(w(o, cb + 8), w(o, cb + 9), var);
        v.w = encpair(w(o + 8, cb + 8), w(o + 8, cb + 9), var);
        g_wE[idx] = v;
    }
    for (int idx = i; idx < 8 * 2 * 2 * 32; idx += nt) {
        int lane = idx & 31, r = idx >> 5;
        int mt = r & 1; r >>= 1;
        int var = r & 1; r >>= 1;
        int kc = r;
        int o = 16 * mt + (lane >> 2);
        int cb = kc * 16 + 2 * (lane & 3);
        auto w = [&](int oo, int d) { return w_in[oo * 128 + d]; };
        uint4 v;
        v.x = encpair(w(o, cb), w(o, cb + 1), var);
        v.y = encpair(w(o + 8, cb), w(o + 8, cb + 1), var);
        v.z = encpair(w(o, cb + 8), w(o, cb + 9), var);
        v.w = encpair(w(o + 8, cb + 8), w(o + 8, cb + 9), var);
        g_wIn[idx] = v;
    }
    for (int idx = i; idx < 2 * 2 * 2 * 32; idx += nt) {
        int lane = idx & 31, r = idx >> 5;
        int mt = r & 1; r >>= 1;
        int var = r & 1; r >>= 1;
        int kt = r;
        int o = 16 * mt + (lane >> 2);
        int cb = kt * 16 + 2 * (lane & 3);
        const float s = 0.40824829046386302f;
        auto w = [&](int oo, int c) { return w_o1[oo * 32 + c] * s; };
        uint4 v;
        v.x = encpair(w(o, cb), w(o, cb + 1), var);
        v.y = encpair(w(o + 8, cb), w(o + 8, cb + 1), var);
        v.z = encpair(w(o, cb + 8), w(o, cb + 9), var);
        v.w = encpair(w(o + 8, cb + 8), w(o + 8, cb + 9), var);
        g_wF[idx] = v;
    }
    for (int idx = i; idx < 2 * 2 * 8 * 32; idx += nt) {
        int lane = idx & 31, r = idx >> 5;
        int mt8 = r & 7; r >>= 3;
        int var = r & 1; r >>= 1;
        int kt = r;
        int o = 16 * mt8 + (lane >> 2);
        int cb = kt * 16 + 2 * (lane & 3);
        auto w = [&](int oo, int c) { return w_o2[oo * 32 + c]; };
        uint4 v;
        v.x = encpair(w(o, cb), w(o, cb + 1), var);
        v.y = encpair(w(o + 8, cb), w(o + 8, cb + 1), var);
        v.z = encpair(w(o, cb + 8), w(o, cb + 9), var);
        v.w = encpair(w(o + 8, cb + 8), w(o + 8, cb + 9), var);
        g_wG[idx] = v;
    }
    if (i == 0) {
        double abar = 1.0;
        for (int t = 0; t < NSTEPS; t++) {
            double beta = 1e-4 + (double)t * (0.1 - 1e-4) / 49.0;
            double alpha = 1.0 - beta, abp = abar;
            abar *= alpha;
            double om = 1.0 - abar;
            g_coef[t * 5 + 0] = (float)sqrt(om);
            g_coef[t * 5 + 1] = (float)(1.0 / sqrt(abar));
            g_coef[t * 5 + 2] = (float)(beta * sqrt(abp) / om);
            g_coef[t * 5 + 3] = (float)((1.0 - abp) * sqrt(alpha) / om);
            double pv = beta * (1.0 - abp) / om;
            g_coef[t * 5 + 4] = (t > 0) ? (float)sqrt(pv) : 0.0f;
        }
    }
}

__global__ void k_stats(const float* __restrict__ x_hist) {
    int b = blockIdx.x, d = threadIdx.x;
    const float* xb = x_hist + (size_t)b * 192 * 128 + d;
    double s = 0.0;
    for (int t = 0; t < 192; t++) s += (double)xb[t * 128];
    float mean = (float)(s / 192.0);
    float c = xb[0] - mean;
    float v = c * c;
    for (int t = 1; t < 192; t++) {
        float cc = xb[t * 128] - mean;
        v = 0.94f * v + 0.06f * (cc * cc);
    }
    g_loc[b * 128 + d] = mean;
    g_scale[b * 128 + d] = fmaxf(sqrtf(v * 0.5f), 1e-5f);
}

__global__ void k_temb(const float* __restrict__ w1, const float* __restrict__ b1,
                       const float* __restrict__ w2, const float* __restrict__ b2,
                       const float* __restrict__ wt, const float* __restrict__ bt) {
    __shared__ float pe[128], te1[512], te2[512];
    int t = blockIdx.x, tid = threadIdx.x;
    if (tid < 64) {
        float y = ((float)tid * 4.0f) / 63.0f;
        float p = (float)pow(10.0, (double)y);
        float e = (float)t * p;
        pe[tid] = (float)sin((double)e);
        pe[tid + 64] = (float)cos((double)e);
    }
    __syncthreads();
    {
        double a = (double)b1[tid];
        for (int j = 0; j < 128; j++) a += (double)pe[j] * (double)w1[j * 512 + tid];
        te1[tid] = (float)(a / (1.0 + exp(-a)));
    }
    __syncthreads();
    {
        double a = (double)b2[tid];
        for (int k = 0; k < 512; k++) a += (double)te1[k] * (double)w2[k * 512 + tid];
        te2[tid] = (float)(a / (1.0 + exp(-a)));
    }
    __syncthreads();
    if (tid < 192) {
        int l = tid >> 5, c = tid & 31;
        double a = (double)bt[l * 32 + c];
        for (int k = 0; k < 512; k++) a += (double)te2[k] * (double)wt[(l * 512 + k) * 32 + c];
        g_cond[(l * NSTEPS + t) * 32 + c] = (float)a;
    }
}

// Pure-fp16 conv (hi term only): 1 A-frag + 2 B-words + 3 MMAs per (tp,kt) pass.
__device__ __forceinline__ void conv_mma(const __half* hT,
                                         __half* aT_hi, __half* aT_lo,
                                         const float* __restrict__ bdil,
                                         int l, int dil, int w, int lane) {
    const int frow = lane >> 2, fcol = 2 * (lane & 3);
    float bg = bdil[l * 64 + 8 * w + frow], bf = bdil[l * 64 + 32 + 8 * w + frow];
    float acc[3][4];
#pragma unroll
    for (int n = 0; n < 3; n++) { acc[n][0] = bg; acc[n][1] = bg; acc[n][2] = bf; acc[n][3] = bf; }
#pragma unroll
    for (int tp = 0; tp < 3; tp++)
#pragma unroll
        for (int kt = 0; kt < 2; kt++) {
            int base = ((((l * 3 + tp) * 2 + kt) * 2) * 4 + w) * 32 + lane;
            uint4 Ah = g_wA[base];
            int r0 = 32 + frow + (tp - 1) * dil;
            int coff = kt * 16 + fcol;
            u32 b0[3], b1[3];
#pragma unroll
            for (int n = 0; n < 3; n++) {
                int c = (r0 + n * 8) * HT + coff;
                b0[n] = *(const u32*)&hT[c]; b1[n] = *(const u32*)&hT[c + 8];
            }
#pragma unroll
            for (int n = 0; n < 3; n++) mma16816(acc[n], Ah, b0[n], b1[n]);
        }
    int o = 8 * w + frow;
#pragma unroll
    for (int n = 0; n < 3; n++) {
        int j = n * 8 + fcol;
        wsplit(aT_hi, aT_lo, j * HT + o, tanh_hw(acc[n][2]) * sigm_hw(acc[n][0]));
        wsplit(aT_hi, aT_lo, (j + 1) * HT + o, tanh_hw(acc[n][3]) * sigm_hw(acc[n][1]));
    }
}

__global__ __launch_bounds__(128, 4) void k_main(
    const float* __restrict__ z_init, const float* __restrict__ noise,
    const float* __restrict__ b_in, const float* __restrict__ bdil,
    const float* __restrict__ bout, const float* __restrict__ b_o1,
    const float* __restrict__ b_o2, float* __restrict__ out) {
    extern __shared__ __align__(16) char dyn[];
    __half* hT = (__half*)dyn;                       // 88*40*2 = 7040 (hi only)
    __half* aT_hi = (__half*)(dyn + 7040);           // 24*40*2 = 1920
    __half* aT_lo = (__half*)(dyn + 8960);
    __half* skT_hi = (__half*)(dyn + 10880);
    __half* skT_lo = (__half*)(dyn + 12800);
    __half* xT_hi = (__half*)(dyn + 14720);          // 24*136*2 = 6528
    __half* xT_lo = (__half*)(dyn + 21248);
    float* nzS = (float*)(dyn + 27776);              // 12288 -> 40064

    const int tid = threadIdx.x, chain = blockIdx.x;
    const int lane = tid & 31, warp = tid >> 5;
    const int frow = lane >> 2, fcol = 2 * (lane & 3);
    const unsigned nz_dst = (unsigned)__cvta_generic_to_shared(&nzS[tid * 24]);

    {
        const float4* zp = (const float4*)(z_init + (size_t)chain * 3072);
#pragma unroll
        for (int q = 0; q < 6; q++) {
            float4 v = zp[tid * 6 + q];
            int j = 4 * q;
            wsplit(xT_hi, xT_lo, j * XT + tid, v.x);
            wsplit(xT_hi, xT_lo, (j + 1) * XT + tid, v.y);
            wsplit(xT_hi, xT_lo, (j + 2) * XT + tid, v.z);
            wsplit(xT_hi, xT_lo, (j + 3) * XT + tid, v.w);
        }
    }
    for (int i = tid; i < 88 * HT / 2; i += 128) ((u32*)hT)[i] = 0u;
    __syncthreads();

    float fR[3][4];

    for (int t = NSTEPS - 1; t >= 0; t--) {
        const float s1m = g_coef[t * 5], isab = g_coef[t * 5 + 1];
        const float c0 = g_coef[t * 5 + 2], cxt = g_coef[t * 5 + 3], sg = g_coef[t * 5 + 4];
        {
            const float* nsrc = noise + ((size_t)(NSTEPS - 1 - t) * 512 + chain) * 3072 + (size_t)tid * 24;
#pragma unroll
            for (int q = 0; q < 6; q++) cpasync16(nz_dst + 16 * q, nsrc + 4 * q);
            asm volatile("cp.async.commit_group;");
        }
        // A: h = relu(W_in @ x + b), warps 0-1 (3-term; fragments = res-warp h state)
        if (warp < 2) {
            int c = 16 * warp + frow;
            float b0 = b_in[c], b8 = b_in[c + 8];
            float cn0 = g_cond[t * 32 + c], cn8 = g_cond[t * 32 + c + 8];
            float acc[3][4];
#pragma unroll
            for (int n = 0; n < 3; n++) { acc[n][0] = b0; acc[n][1] = b0; acc[n][2] = b8; acc[n][3] = b8; }
#pragma unroll
            for (int kc = 0; kc < 8; kc++) {
                int base = ((kc * 2) * 2 + warp) * 32 + lane;
                uint4 Ah = g_wIn[base], Al = g_wIn[base + 64];
                u32 bh0[3], bh1[3], bl0[3], bl1[3];
#pragma unroll
                for (int n = 0; n < 3; n++) {
                    int coff = (n * 8 + frow) * XT + kc * 16 + fcol;
                    bh0[n] = *(const u32*)&xT_hi[coff]; bh1[n] = *(const u32*)&xT_hi[coff + 8];
                    bl0[n] = *(const u32*)&xT_lo[coff]; bl1[n] = *(const u32*)&xT_lo[coff + 8];
                }
#pragma unroll
                for (int n = 0; n < 3; n++) mma16816(acc[n], Ah, bh0[n], bh1[n]);
#pragma unroll
                for (int n = 0; n < 3; n++) mma16816(acc[n], Ah, bl0[n], bl1[n]);
#pragma unroll
                for (int n = 0; n < 3; n++) mma16816(acc[n], Al, bh0[n], bh1[n]);
            }
#pragma unroll
            for (int n = 0; n < 3; n++) {
                int j = n * 8 + fcol;
#pragma unroll
                for (int q = 0; q < 4; q++) fR[n][q] = fmaxf(acc[n][q], 0.f);
                hT[(32 + j) * HT + c] = __float2half_rn(fR[n][0] + cn0);
                hT[(33 + j) * HT + c] = __float2half_rn(fR[n][1] + cn0);
                hT[(32 + j) * HT + c + 8] = __float2half_rn(fR[n][2] + cn8);
                hT[(33 + j) * HT + c + 8] = __float2half_rn(fR[n][3] + cn8);
            }
        } else {
#pragma unroll
            for (int n = 0; n < 3; n++) { fR[n][0] = 0.f; fR[n][1] = 0.f; fR[n][2] = 0.f; fR[n][3] = 0.f; }
        }
        __syncthreads();

        int dil = 1;
        for (int l = 0; l < 6; l++, dil <<= 1) {
            conv_mma(hT, aT_hi, aT_lo, bdil, l, dil, warp, lane);
            __syncthreads();
            {
                bool resw = (warp < 2);
                if (resw ? (l < 5) : true) {
                    int c = resw ? 16 * warp + frow : 16 * (warp - 2) + frow;
                    int ob = resw ? c : 32 + c;
                    float b0 = bout[l * 64 + ob], b8 = bout[l * 64 + ob + 8];
                    float acc[3][4];
#pragma unroll
                    for (int n = 0; n < 3; n++) { acc[n][0] = b0; acc[n][1] = b0; acc[n][2] = b8; acc[n][3] = b8; }
#pragma unroll
                    for (int kt = 0; kt < 2; kt++) {
                        int base = (((l * 2 + kt) * 2) * 4 + warp) * 32 + lane;
                        uint4 Ah = g_wE[base], Al = g_wE[base + 128];
                        mma3x3(acc, Ah, Al, aT_hi, aT_lo, frow, 8, kt * 16 + fcol);
                    }
                    if (resw) {
                        float cn0 = g_cond[((l + 1) * NSTEPS + t) * 32 + c];
                        float cn8 = g_cond[((l + 1) * NSTEPS + t) * 32 + c + 8];
#pragma unroll
                        for (int n = 0; n < 3; n++) {
                            int j = n * 8 + fcol;
#pragma unroll
                            for (int q = 0; q < 4; q++)
                                fR[n][q] = (fR[n][q] + acc[n][q]) * 0.70710678118654752f;
                            hT[(32 + j) * HT + c] = __float2half_rn(fR[n][0] + cn0);
                            hT[(33 + j) * HT + c] = __float2half_rn(fR[n][1] + cn0);
                            hT[(32 + j) * HT + c + 8] = __float2half_rn(fR[n][2] + cn8);
                            hT[(33 + j) * HT + c + 8] = __float2half_rn(fR[n][3] + cn8);
                        }
                    } else {
#pragma unroll
                        for (int n = 0; n < 3; n++) {
#pragma unroll
                            for (int q = 0; q < 4; q++) fR[n][q] += acc[n][q];
                        }
                        if (l == 5) {
#pragma unroll
                            for (int n = 0; n < 3; n++) {
                                int j = n * 8 + fcol;
                                wsplit(skT_hi, skT_lo, j * HT + c, fR[n][0]);
                                wsplit(skT_hi, skT_lo, (j + 1) * HT + c, fR[n][1]);
                                wsplit(skT_hi, skT_lo, j * HT + c + 8, fR[n][2]);
                                wsplit(skT_hi, skT_lo, (j + 1) * HT + c + 8, fR[n][3]);
                            }
                        }
                    }
                }
            }
            __syncthreads();
        }
        // F: s = relu(W_o1 @ skip/sqrt6 + b), warps 0-1 -> aT
        if (warp < 2) {
            int c = 16 * warp + frow;
            float b0 = b_o1[c], b8 = b_o1[c + 8];
            float acc[3][4];
#pragma unroll
            for (int n = 0; n < 3; n++) { acc[n][0] = b0; acc[n][1] = b0; acc[n][2] = b8; acc[n][3] = b8; }
#pragma unroll
            for (int kt = 0; kt < 2; kt++) {
                int base = ((kt * 2) * 2 + warp) * 32 + lane;
                uint4 Ah = g_wF[base], Al = g_wF[base + 64];
                mma3x3(acc, Ah, Al, skT_hi, skT_lo, frow, 8, kt * 16 + fcol);
            }
#pragma unroll
            for (int n = 0; n < 3; n++) {
                int j = n * 8 + fcol;
                wsplit(aT_hi, aT_lo, j * HT + c, fmaxf(acc[n][0], 0.f));
                wsplit(aT_hi, aT_lo, (j + 1) * HT + c, fmaxf(acc[n][1], 0.f));
                wsplit(aT_hi, aT_lo, j * HT + c + 8, fmaxf(acc[n][2], 0.f));
                wsplit(aT_hi, aT_lo, (j + 1) * HT + c + 8, fmaxf(acc[n][3], 0.f));
            }
        }
        __syncthreads();
        // G: eps = W_o2 @ s (all warps, 2 m-tiles); DDPM update of split-x
#pragma unroll
        for (int m = 0; m < 2; m++) {
            int mt8 = 2 * warp + m, dbase = 16 * mt8;
            float b0 = b_o2[dbase + frow], b8 = b_o2[dbase + frow + 8];
            float acc[3][4];
#pragma unroll
            for (int n = 0; n < 3; n++) { acc[n][0] = b0; acc[n][1] = b0; acc[n][2] = b8; acc[n][3] = b8; }
#pragma unroll
            for (int kt = 0; kt < 2; kt++) {
                int base = ((kt * 2) * 8 + mt8) * 32 + lane;
                uint4 Ah = g_wG[base], Al = g_wG[base + 256];
                mma3x3(acc, Ah, Al, aT_hi, aT_lo, frow, 8, kt * 16 + fcol);
            }
            if (m == 0) asm volatile("cp.async.wait_group 0;" ::: "memory");
#pragma unroll
            for (int n = 0; n < 3; n++)
#pragma unroll
                for (int r = 0; r < 2; r++) {
                    int d = dbase + frow + 8 * r;
                    int j = n * 8 + fcol;
                    float2 nz = *(const float2*)&nzS[d * 24 + j];
#pragma unroll
                    for (int e = 0; e < 2; e++) {
                        int xa = (j + e) * XT + d;
                        float x = __half2float(xT_hi[xa]) + __half2float(xT_lo[xa]);
                        float eps = acc[n][2 * r + e];
                        float x0 = fminf(fmaxf((x - s1m * eps) * isab, -1.f), 1.f);
                        float xn = fmaf(c0, x0, fmaf(cxt, x, sg * (e ? nz.y : nz.x)));
                        wsplit(xT_hi, xT_lo, xa, xn);
                    }
                }
        }
        __syncthreads();
    }
    {
        int b = chain & 31;
        float lc = g_loc[b * 128 + tid];
        float scl = g_scale[b * 128 + tid];
        for (int hh = 0; hh < 24; hh++) {
            int xa = hh * XT + tid;
            double z = (double)(__half2float(xT_hi[xa]) + __half2float(xT_lo[xa]));
            double u = 0.5 * erfc(-z * 0.70710678118654752440);
            u = fmin(fmax(u, 1e-6), 1.0 - 1e-6);
            double a = 4.0 * u * (1.0 - u);
            a = fmin(fmax(a, 1e-12), 1.0);
            double r = sqrt(a);
            double q = 2.0 * sqrt(fmax(cos(acos(r) / 3.0) / r - 1.0, 0.0));
            double sgn = (u >= 0.5) ? 1.0 : -1.0;
            out[((size_t)chain * 24 + hh) * 128 + tid] = (float)((double)lc + (double)scl * sgn * q);
        }
    }
}

extern "C" void kernel_launch(void* const* d_in, const int* in_sizes, int n_in,
                              void* d_out, int out_size) {
    const float* x_hist = (const float*)d_in[0];
    const float* z_init = (const float*)d_in[1];
    const float* noise = (const float*)d_in[2];
    const float* w_in = (const float*)d_in[3];
    const float* b_in = (const float*)d_in[4];
    const float* tw1 = (const float*)d_in[5];
    const float* tb1 = (const float*)d_in[6];
    const float* tw2 = (const float*)d_in[7];
    const float* tb2 = (const float*)d_in[8];
    const float* lwt = (const float*)d_in[9];
    const float* lbt = (const float*)d_in[10];
    const float* lwd = (const float*)d_in[11];
    const float* lbd = (const float*)d_in[12];
    const float* lwo = (const float*)d_in[13];
    const float* lbo = (const float*)d_in[14];
    const float* w_o1 = (const float*)d_in[15];
    const float* b_o1 = (const float*)d_in[16];
    const float* w_o2 = (const float*)d_in[17];
    const float* b_o2 = (const float*)d_in[18];
    float* out = (float*)d_out;

    const int SMEM = 40064;
    cudaFuncSetAttribute(k_main, cudaFuncAttributeMaxDynamicSharedMemorySize, SMEM);
    k_prep<<<64, 256>>>(w_in, lwd, lwo, w_o1, w_o2);
    k_stats<<<32, 128>>>(x_hist);
    k_temb<<<50, 512>>>(tw1, tb1, tw2, tb2, lwt, lbt);
    k_main<<<512, 128, SMEM>>>(z_init, noise, b_in, lbd, lbo, b_o1, b_o2, out);
}